// round 2
// baseline (speedup 1.0000x reference)
#include <cuda_runtime.h>
#include <math.h>

#define NN   50000
#define NE   800000
#define DIN  500
#define DH   256
#define DOUT 40

// ---------------- scratch (static device globals: allocation-free) ----------
__device__ float g_buf[6][NN * DH];   // 6 x 51.2 MB
__device__ float g_acc[NN * DH];
__device__ float g_S[NN * DH];
__device__ float g_dinv[3 * NN];
__device__ float g_mask[8];

// ---------------- tiny kernels ----------------------------------------------
__global__ void k_mask(const float* __restrict__ att) {
    if (threadIdx.x == 0) {
        float m = -1e30f;
        for (int i = 0; i < 5; i++) m = fmaxf(m, att[i]);
        float e[5], s = 0.f;
        for (int i = 0; i < 5; i++) { e[i] = expf(att[i] - m); s += e[i]; }
        for (int i = 0; i < 5; i++) g_mask[i] = e[i] / s;
    }
}

__global__ void k_fill1(float* __restrict__ p, int n) {
    int i = blockIdx.x * blockDim.x + threadIdx.x;
    if (i < n) p[i] = 1.0f;
}

__global__ void k_deg(const int* __restrict__ ei, float* __restrict__ dinv) {
    int i = blockIdx.x * blockDim.x + threadIdx.x;
    if (i >= 3 * NE) return;
    int g = i / NE;
    int e = i - g * NE;
    int d = ei[(g * 2 + 1) * NE + e];
    atomicAdd(&dinv[g * NN + d], 1.0f);
}

__global__ void k_rsqrt(float* __restrict__ p, int n) {
    int i = blockIdx.x * blockDim.x + threadIdx.x;
    if (i < n) p[i] = rsqrtf(p[i]);   // deg >= 1 always (self loop)
}

// S[i,:] = hw[i,:] * dinv[i]^2   (self-loop contribution, initializes S)
__global__ void k_selfloop(const float* __restrict__ hw,
                           const float* __restrict__ dinv,
                           float* __restrict__ S) {
    int i = blockIdx.x * blockDim.x + threadIdx.x;
    if (i >= NN * (DH / 4)) return;
    int node = i / (DH / 4);
    float dv = dinv[node];
    float w = dv * dv;
    float4 v = ((const float4*)hw)[i];
    v.x *= w; v.y *= w; v.z *= w; v.w *= w;
    ((float4*)S)[i] = v;
}

// warp per edge: S[dst] += hw[src] * dinv[src]*dinv[dst]
// result-unused atomicAdd lowers to RED (fire-and-forget reduction).
__global__ void k_scatter(const int* __restrict__ src, const int* __restrict__ dst,
                          const float* __restrict__ dinv,
                          const float* __restrict__ hw, float* __restrict__ S) {
    int gw = (blockIdx.x * blockDim.x + threadIdx.x) >> 5;
    if (gw >= NE) return;
    int lane = threadIdx.x & 31;
    int s = src[gw], d = dst[gw];
    float w = dinv[s] * dinv[d];
    const float4* h = (const float4*)(hw + (size_t)s * DH);
    float* o = S + (size_t)d * DH;
    float4 v0 = h[lane];
    float4 v1 = h[lane + 32];
    int c0 = lane * 4, c1 = (lane + 32) * 4;
    atomicAdd(o + c0 + 0, v0.x * w);
    atomicAdd(o + c0 + 1, v0.y * w);
    atomicAdd(o + c0 + 2, v0.z * w);
    atomicAdd(o + c0 + 3, v0.w * w);
    atomicAdd(o + c1 + 0, v1.x * w);
    atomicAdd(o + c1 + 1, v1.y * w);
    atomicAdd(o + c1 + 2, v1.z * w);
    atomicAdd(o + c1 + 3, v1.w * w);
}

// out = relu(S + bias)            (ACCUM=false)
// out += relu(S + bias) * *mask   (ACCUM=true)
template <bool ACCUM>
__global__ void k_post(const float* __restrict__ S, const float* __restrict__ bias,
                       const float* __restrict__ maskPtr, float* __restrict__ out) {
    int i = blockIdx.x * blockDim.x + threadIdx.x;
    if (i >= NN * (DH / 4)) return;
    int c4 = i & (DH / 4 - 1);
    float4 b = ((const float4*)bias)[c4];
    float4 v = ((const float4*)S)[i];
    v.x = fmaxf(v.x + b.x, 0.f);
    v.y = fmaxf(v.y + b.y, 0.f);
    v.z = fmaxf(v.z + b.z, 0.f);
    v.w = fmaxf(v.w + b.w, 0.f);
    if (ACCUM) {
        float m = *maskPtr;
        float4 o = ((float4*)out)[i];
        o.x += v.x * m; o.y += v.y * m; o.z += v.z * m; o.w += v.w * m;
        ((float4*)out)[i] = o;
    } else {
        ((float4*)out)[i] = v;
    }
}

// ---------------- SGEMM: C[M,N] = A[M,K] @ B[K,N]  (row-major) --------------
// 128x128 tile, BK=16, 256 threads, 8x8 microtile.
// Optional epilogue: +bias[col], relu, * (*scalePtr).
template <bool BIAS, bool RELU, bool SCALE>
__global__ void __launch_bounds__(256)
sgemm_k(const float* __restrict__ A, const float* __restrict__ B,
        const float* __restrict__ bias, const float* __restrict__ scalePtr,
        float* __restrict__ C, int M, int N, int K) {
    __shared__ float As[16][129];   // [k][m], +1 pad
    __shared__ float Bs[16][128];   // [k][n]

    const int bm = blockIdx.x * 128;
    const int bn = blockIdx.y * 128;
    const int tid = threadIdx.x;
    const int tx = tid & 15;    // 16 col groups
    const int ty = tid >> 4;    // 16 row groups

    float acc[8][8];
#pragma unroll
    for (int i = 0; i < 8; i++)
#pragma unroll
        for (int j = 0; j < 8; j++) acc[i][j] = 0.f;

    for (int k0 = 0; k0 < K; k0 += 16) {
        // load A tile (128 x 16): linear -> m = lin/16, k = lin%16
#pragma unroll
        for (int i = 0; i < 8; i++) {
            int lin = tid + i * 256;
            int m = lin >> 4, kk = lin & 15;
            int row = bm + m, col = k0 + kk;
            As[kk][m] = (row < M && col < K) ? A[(size_t)row * K + col] : 0.f;
        }
        // load B tile (16 x 128): linear -> k = lin/128, n = lin%128
#pragma unroll
        for (int i = 0; i < 8; i++) {
            int lin = tid + i * 256;
            int kk = lin >> 7, n = lin & 127;
            int row = k0 + kk, col = bn + n;
            Bs[kk][n] = (row < K && col < N) ? B[(size_t)row * N + col] : 0.f;
        }
        __syncthreads();

#pragma unroll
        for (int kk = 0; kk < 16; kk++) {
            float a[8], b[8];
#pragma unroll
            for (int i = 0; i < 4; i++) {
                a[i]     = As[kk][ty * 4 + i];
                a[4 + i] = As[kk][64 + ty * 4 + i];
            }
            float4 b0 = *(const float4*)&Bs[kk][tx * 4];
            float4 b1 = *(const float4*)&Bs[kk][64 + tx * 4];
            b[0] = b0.x; b[1] = b0.y; b[2] = b0.z; b[3] = b0.w;
            b[4] = b1.x; b[5] = b1.y; b[6] = b1.z; b[7] = b1.w;
#pragma unroll
            for (int i = 0; i < 8; i++)
#pragma unroll
                for (int j = 0; j < 8; j++) acc[i][j] += a[i] * b[j];
        }
        __syncthreads();
    }

    float scale = SCALE ? *scalePtr : 1.f;
#pragma unroll
    for (int i = 0; i < 8; i++) {
        int row = bm + ((i < 4) ? (ty * 4 + i) : (64 + ty * 4 + i - 4));
        if (row >= M) continue;
#pragma unroll
        for (int j = 0; j < 8; j++) {
            int col = bn + ((j < 4) ? (tx * 4 + j) : (64 + tx * 4 + j - 4));
            if (col >= N) continue;
            float v = acc[i][j];
            if (BIAS) v += bias[col];
            if (RELU) v = fmaxf(v, 0.f);
            if (SCALE) v *= scale;
            C[(size_t)row * N + col] = v;
        }
    }
}

// ---------------- in-place log-softmax over rows of 40 ----------------------
__global__ void k_lsm(float* __restrict__ p, int M) {
    int row = blockIdx.x * 8 + (threadIdx.x >> 5);
    int lane = threadIdx.x & 31;
    if (row >= M) return;
    float* r = p + (size_t)row * DOUT;
    float x0 = r[lane];                               // lane < 32 < 40
    float x1 = (lane < 8) ? r[lane + 32] : -1e30f;    // cols 32..39
    float m = fmaxf(x0, x1);
#pragma unroll
    for (int o = 16; o > 0; o >>= 1) m = fmaxf(m, __shfl_xor_sync(0xffffffffu, m, o));
    float s = expf(x0 - m) + ((lane < 8) ? expf(x1 - m) : 0.f);
#pragma unroll
    for (int o = 16; o > 0; o >>= 1) s += __shfl_xor_sync(0xffffffffu, s, o);
    float l = m + logf(s);
    r[lane] = x0 - l;
    if (lane < 8) r[lane + 32] = x1 - l;
}

// ---------------- launch ----------------------------------------------------
extern "C" void kernel_launch(void* const* d_in, const int* in_sizes, int n_in,
                              void* d_out, int out_size) {
    const float* x       = (const float*)d_in[0];
    const int*   ei      = (const int*)  d_in[1];
    const float* att     = (const float*)d_in[2];
    const float* W_mlp   = (const float*)d_in[3];
    const float* b_mlp   = (const float*)d_in[4];
    const float* W_mlp2  = (const float*)d_in[5];
    const float* b_mlp2  = (const float*)d_in[6];
    const float* W_init  = (const float*)d_in[7];
    const float* b_init  = (const float*)d_in[8];
    const float* W_init2 = (const float*)d_in[9];
    const float* b_init2 = (const float*)d_in[10];
    const float* W_convs = (const float*)d_in[11];
    const float* b_convs = (const float*)d_in[12];
    const float* fc1_W   = (const float*)d_in[13];
    const float* fc1_b   = (const float*)d_in[14];
    float* out = (float*)d_out;

    float *bufbase, *accp, *Sp, *dinvp, *maskp;
    cudaGetSymbolAddress((void**)&bufbase, g_buf);
    cudaGetSymbolAddress((void**)&accp,    g_acc);
    cudaGetSymbolAddress((void**)&Sp,      g_S);
    cudaGetSymbolAddress((void**)&dinvp,   g_dinv);
    cudaGetSymbolAddress((void**)&maskp,   g_mask);
    float* buf[6];
    for (int i = 0; i < 6; i++) buf[i] = bufbase + (size_t)i * NN * DH;

    const int T = 256;
    const int n4b    = (NN * (DH / 4) + T - 1) / T;
    const int scat_b = (NE * 32 + T - 1) / T;
    dim3 gH((NN + 127) / 128, (DH + 127) / 128);
    dim3 gO((NN + 127) / 128, (DOUT + 127) / 128);

    // prep: softmax mask, degrees
    k_mask<<<1, 32>>>(att);
    k_fill1<<<(3 * NN + T - 1) / T, T>>>(dinvp, 3 * NN);
    k_deg<<<(3 * NE + T - 1) / T, T>>>(ei, dinvp);
    k_rsqrt<<<(3 * NN + T - 1) / T, T>>>(dinvp, 3 * NN);

    // X-side GEMMs
    sgemm_k<false, false, false><<<gH, T>>>(x, W_init, nullptr, nullptr, buf[0], NN, DH, DIN);
    for (int i = 0; i < 3; i++)
        sgemm_k<false, false, false><<<gH, T>>>(x, W_convs + (size_t)i * DIN * DH,
                                                nullptr, nullptr, buf[1 + i], NN, DH, DIN);
    sgemm_k<true, true, false><<<gH, T>>>(x, W_mlp, b_mlp, nullptr, buf[4], NN, DH, DIN);

    // MLP branch initializes acc: acc = relu(H1 @ W_mlp2 + b) * mask[3]
    sgemm_k<true, true, true><<<gH, T>>>(buf[4], W_mlp2, b_mlp2, maskp + 3, accp, NN, DH, DH);

    const int* src2 = ei + (2 * 2 + 0) * NE;
    const int* dst2 = ei + (2 * 2 + 1) * NE;

    // init branch, hop 1: e1 = relu(gcn(x, W_init, g2))
    k_selfloop<<<n4b, T>>>(buf[0], dinvp + 2 * NN, Sp);
    k_scatter<<<scat_b, T>>>(src2, dst2, dinvp + 2 * NN, buf[0], Sp);
    k_post<false><<<n4b, T>>>(Sp, b_init, nullptr, buf[5]);

    // hop 2: acc += relu(gcn(e1, W_init2, g2)) * mask[4]
    sgemm_k<false, false, false><<<gH, T>>>(buf[5], W_init2, nullptr, nullptr, buf[0], NN, DH, DH);
    k_selfloop<<<n4b, T>>>(buf[0], dinvp + 2 * NN, Sp);
    k_scatter<<<scat_b, T>>>(src2, dst2, dinvp + 2 * NN, buf[0], Sp);
    k_post<true><<<n4b, T>>>(Sp, b_init2, maskp + 4, accp);

    // conv layers: acc += relu(gcn(x, W_convs[i], g_i)) * mask[i]
    for (int i = 0; i < 3; i++) {
        const int* s = ei + (i * 2 + 0) * NE;
        const int* d = ei + (i * 2 + 1) * NE;
        k_selfloop<<<n4b, T>>>(buf[1 + i], dinvp + i * NN, Sp);
        k_scatter<<<scat_b, T>>>(s, d, dinvp + i * NN, buf[1 + i], Sp);
        k_post<true><<<n4b, T>>>(Sp, b_convs + (size_t)i * DH, maskp + i, accp);
    }

    // logits + log-softmax
    sgemm_k<true, false, false><<<gO, T>>>(accp, fc1_W, fc1_b, nullptr, out, NN, DOUT, DH);
    k_lsm<<<(NN + 7) / 8, 256>>>(out, NN);
}

// round 3
// speedup vs baseline: 1.7138x; 1.7138x over previous
#include <cuda_runtime.h>
#include <math.h>
#include <stdint.h>

#define NN   50000
#define NE   800000
#define DIN  500
#define DH   256
#define NC   1280     // packed columns: [W_init | W_conv0 | W_conv1 | W_conv2 | W_mlp]
#define DOUT 40

// ---------------- scratch (static device globals: allocation-free) ----------
__device__ float g_C[(size_t)NN * NC];   // packed X-side GEMM outputs (256 MB)
__device__ float g_h[NN * DH];           // hop-1 output of init branch
__device__ float g_hw2[NN * DH];         // hop-2 hw
__device__ float g_acc[NN * DH];
__device__ float g_S[NN * DH];
__device__ float g_W[DIN * NC];          // packed weights
__device__ float g_dinv[3 * NN];
__device__ float g_mask[8];

// ---------------- tiny kernels ----------------------------------------------
__global__ void k_mask(const float* __restrict__ att) {
    if (threadIdx.x == 0) {
        float m = -1e30f;
        for (int i = 0; i < 5; i++) m = fmaxf(m, att[i]);
        float e[5], s = 0.f;
        for (int i = 0; i < 5; i++) { e[i] = expf(att[i] - m); s += e[i]; }
        for (int i = 0; i < 5; i++) g_mask[i] = e[i] / s;
    }
}

__global__ void k_fill1(float* __restrict__ p, int n) {
    int i = blockIdx.x * blockDim.x + threadIdx.x;
    if (i < n) p[i] = 1.0f;
}

__global__ void k_deg(const int* __restrict__ ei, float* __restrict__ dinv) {
    int i = blockIdx.x * blockDim.x + threadIdx.x;
    if (i >= 3 * NE) return;
    int g = i / NE;
    int e = i - g * NE;
    int d = ei[(g * 2 + 1) * NE + e];
    atomicAdd(&dinv[g * NN + d], 1.0f);
}

__global__ void k_rsqrt(float* __restrict__ p, int n) {
    int i = blockIdx.x * blockDim.x + threadIdx.x;
    if (i < n) p[i] = rsqrtf(p[i]);
}

// pack weights: g_W[k][n], slice s=n/256 -> {W_init, W_conv0..2, W_mlp}
__global__ void k_pack(const float* __restrict__ Wi, const float* __restrict__ Wc,
                       const float* __restrict__ Wm, float* __restrict__ Wcat) {
    int i = blockIdx.x * blockDim.x + threadIdx.x;
    if (i >= DIN * NC) return;
    int k = i / NC, n = i - k * NC;
    int s = n >> 8, c = n & 255;
    float v;
    if (s == 0)      v = Wi[k * DH + c];
    else if (s <= 3) v = Wc[(size_t)(s - 1) * DIN * DH + k * DH + c];
    else             v = Wm[k * DH + c];
    Wcat[i] = v;
}

// S[i,:] = hw[i,:] * dinv[i]^2 ; hw row stride = ldh floats
__global__ void k_selfloop(const float* __restrict__ hw, int ldh,
                           const float* __restrict__ dinv, float* __restrict__ S) {
    int i = blockIdx.x * blockDim.x + threadIdx.x;
    if (i >= NN * (DH / 4)) return;
    int node = i >> 6, c4 = i & 63;
    float dv = dinv[node];
    float w = dv * dv;
    float4 v = *(const float4*)(hw + (size_t)node * ldh + c4 * 4);
    v.x *= w; v.y *= w; v.z *= w; v.w *= w;
    ((float4*)S)[i] = v;
}

// warp per edge: S[dst] += hw[src] * dinv[src]*dinv[dst]
__global__ void k_scatter(const int* __restrict__ src, const int* __restrict__ dst,
                          const float* __restrict__ dinv,
                          const float* __restrict__ hw, int ldh, float* __restrict__ S) {
    int gw = (blockIdx.x * blockDim.x + threadIdx.x) >> 5;
    if (gw >= NE) return;
    int lane = threadIdx.x & 31;
    int s = src[gw], d = dst[gw];
    float w = dinv[s] * dinv[d];
    const float4* h = (const float4*)(hw + (size_t)s * ldh);
    float* o = S + (size_t)d * DH;
    float4 v0 = h[lane];
    float4 v1 = h[lane + 32];
    int c0 = lane * 4, c1 = (lane + 32) * 4;
    atomicAdd(o + c0 + 0, v0.x * w);
    atomicAdd(o + c0 + 1, v0.y * w);
    atomicAdd(o + c0 + 2, v0.z * w);
    atomicAdd(o + c0 + 3, v0.w * w);
    atomicAdd(o + c1 + 0, v1.x * w);
    atomicAdd(o + c1 + 1, v1.y * w);
    atomicAdd(o + c1 + 2, v1.z * w);
    atomicAdd(o + c1 + 3, v1.w * w);
}

template <bool ACCUM>
__global__ void k_post(const float* __restrict__ S, const float* __restrict__ bias,
                       const float* __restrict__ maskPtr, float* __restrict__ out) {
    int i = blockIdx.x * blockDim.x + threadIdx.x;
    if (i >= NN * (DH / 4)) return;
    int c4 = i & 63;
    float4 b = ((const float4*)bias)[c4];
    float4 v = ((const float4*)S)[i];
    v.x = fmaxf(v.x + b.x, 0.f);
    v.y = fmaxf(v.y + b.y, 0.f);
    v.z = fmaxf(v.z + b.z, 0.f);
    v.w = fmaxf(v.w + b.w, 0.f);
    if (ACCUM) {
        float m = *maskPtr;
        float4 o = ((float4*)out)[i];
        o.x += v.x * m; o.y += v.y * m; o.z += v.z * m; o.w += v.w * m;
        ((float4*)out)[i] = o;
    } else {
        ((float4*)out)[i] = v;
    }
}

// ---------------- tf32 tensor-core GEMM -------------------------------------
// C[M,N] = A[M,K] @ B[K,N] row-major; lda/ldb/ldc row strides.
// 128x128 tile, BK=16, 256 threads, warp tile 32x64 (m16n8k8 tf32 mma).
// Epilogue (cols >= col0): +bias[col-col0], relu; scale applies to all cols.
__device__ __forceinline__ uint32_t f2tf(float f) {
    uint32_t u; asm("cvt.rna.tf32.f32 %0, %1;" : "=r"(u) : "f"(f)); return u;
}
__device__ __forceinline__ void cpa16(uint32_t dst, const void* src, bool pred) {
    int sz = pred ? 16 : 0;
    asm volatile("cp.async.cg.shared.global [%0], [%1], 16, %2;\n"
                 :: "r"(dst), "l"(src), "r"(sz));
}

#define AS_STRIDE 20    // 16 k + 4 pad  (stride%32==20 -> conflict-free A frags)
#define BS_STRIDE 136   // 128 n + 8 pad (stride%32==8  -> conflict-free B frags)

template <bool BIAS, bool RELU, bool SCALE>
__global__ void __launch_bounds__(256, 2)
gemm_tf32(const float* __restrict__ A, const float* __restrict__ B,
          const float* __restrict__ bias, const float* __restrict__ scalePtr,
          float* __restrict__ C, int M, int N, int K,
          int lda, int ldb, int ldc, int col0) {
    __shared__ float As[2][128 * AS_STRIDE];
    __shared__ float Bs[2][16 * BS_STRIDE];

    const int tid  = threadIdx.x;
    const int bm   = blockIdx.y * 128;
    const int bn   = blockIdx.x * 128;
    const int wid  = tid >> 5, lane = tid & 31;
    const int wm   = (wid >> 1) * 32;      // 4 warp rows
    const int wn   = (wid & 1) * 64;       // 2 warp cols
    const int g    = lane >> 2, q = lane & 3;

    float4 acc[2][8];
#pragma unroll
    for (int i = 0; i < 2; i++)
#pragma unroll
        for (int j = 0; j < 8; j++) acc[i][j] = make_float4(0.f, 0.f, 0.f, 0.f);

    const uint32_t sA = (uint32_t)__cvta_generic_to_shared(&As[0][0]);
    const uint32_t sB = (uint32_t)__cvta_generic_to_shared(&Bs[0][0]);
    const uint32_t aBufSz = 128 * AS_STRIDE * 4;
    const uint32_t bBufSz = 16 * BS_STRIDE * 4;

    const int T = (K + 15) / 16;

    // tile loader: per thread 2 A-chunks + 2 B-chunks of 16B
    auto load_tile = [&](int t, int buf) {
        int k0 = t * 16;
#pragma unroll
        for (int i = 0; i < 2; i++) {
            int c = tid + i * 256;
            int m = c >> 2, k = (c & 3) * 4;
            const float* srcp = A + (size_t)(bm + m) * lda + k0 + k;
            bool p = (bm + m < M) && (k0 + k < K);
            cpa16(sA + buf * aBufSz + (uint32_t)(m * AS_STRIDE + k) * 4, srcp, p);
        }
#pragma unroll
        for (int i = 0; i < 2; i++) {
            int c = tid + i * 256;
            int kk = c >> 5, n = (c & 31) * 4;
            const float* srcp = B + (size_t)(k0 + kk) * ldb + bn + n;
            bool p = (k0 + kk < K) && (bn + n < N);
            cpa16(sB + buf * bBufSz + (uint32_t)(kk * BS_STRIDE + n) * 4, srcp, p);
        }
    };

    load_tile(0, 0);
    asm volatile("cp.async.commit_group;\n" ::);

    for (int t = 0; t < T; t++) {
        if (t + 1 < T) {
            load_tile(t + 1, (t + 1) & 1);
            asm volatile("cp.async.commit_group;\n" ::);
            asm volatile("cp.async.wait_group 1;\n" ::);
        } else {
            asm volatile("cp.async.wait_group 0;\n" ::);
        }
        __syncthreads();

        const float* as = As[t & 1];
        const float* bs = Bs[t & 1];
#pragma unroll
        for (int kp = 0; kp < 2; kp++) {
            const int kb = kp * 8;
            uint32_t a[2][4], b[8][2];
#pragma unroll
            for (int i = 0; i < 2; i++) {
                int m0 = wm + i * 16;
                a[i][0] = f2tf(as[(m0 + g) * AS_STRIDE + kb + q]);
                a[i][1] = f2tf(as[(m0 + g + 8) * AS_STRIDE + kb + q]);
                a[i][2] = f2tf(as[(m0 + g) * AS_STRIDE + kb + q + 4]);
                a[i][3] = f2tf(as[(m0 + g + 8) * AS_STRIDE + kb + q + 4]);
            }
#pragma unroll
            for (int j = 0; j < 8; j++) {
                int n0 = wn + j * 8;
                b[j][0] = f2tf(bs[(kb + q) * BS_STRIDE + n0 + g]);
                b[j][1] = f2tf(bs[(kb + q + 4) * BS_STRIDE + n0 + g]);
            }
#pragma unroll
            for (int i = 0; i < 2; i++)
#pragma unroll
                for (int j = 0; j < 8; j++) {
                    asm volatile(
                        "mma.sync.aligned.m16n8k8.row.col.f32.tf32.tf32.f32 "
                        "{%0,%1,%2,%3},{%4,%5,%6,%7},{%8,%9},{%0,%1,%2,%3};"
                        : "+f"(acc[i][j].x), "+f"(acc[i][j].y),
                          "+f"(acc[i][j].z), "+f"(acc[i][j].w)
                        : "r"(a[i][0]), "r"(a[i][1]), "r"(a[i][2]), "r"(a[i][3]),
                          "r"(b[j][0]), "r"(b[j][1]));
                }
        }
        __syncthreads();
    }

    float scale = SCALE ? *scalePtr : 1.f;
#pragma unroll
    for (int i = 0; i < 2; i++) {
#pragma unroll
        for (int j = 0; j < 8; j++) {
            int col = bn + wn + j * 8 + q * 2;
            if (col >= N) continue;
            bool ep = (col >= col0);
            float b0 = 0.f, b1 = 0.f;
            if (BIAS && ep) { b0 = bias[col - col0]; b1 = bias[col + 1 - col0]; }
            int r0 = bm + wm + i * 16 + g;
            int r1 = r0 + 8;
            float v0 = acc[i][j].x, v1 = acc[i][j].y;
            float v2 = acc[i][j].z, v3 = acc[i][j].w;
            if (BIAS && ep) { v0 += b0; v1 += b1; v2 += b0; v3 += b1; }
            if (RELU && ep) {
                v0 = fmaxf(v0, 0.f); v1 = fmaxf(v1, 0.f);
                v2 = fmaxf(v2, 0.f); v3 = fmaxf(v3, 0.f);
            }
            if (SCALE) { v0 *= scale; v1 *= scale; v2 *= scale; v3 *= scale; }
            if (r0 < M) *(float2*)(C + (size_t)r0 * ldc + col) = make_float2(v0, v1);
            if (r1 < M) *(float2*)(C + (size_t)r1 * ldc + col) = make_float2(v2, v3);
        }
    }
}

// ---------------- in-place log-softmax over rows of 40 ----------------------
__global__ void k_lsm(float* __restrict__ p, int M) {
    int row = blockIdx.x * 8 + (threadIdx.x >> 5);
    int lane = threadIdx.x & 31;
    if (row >= M) return;
    float* r = p + (size_t)row * DOUT;
    float x0 = r[lane];
    float x1 = (lane < 8) ? r[lane + 32] : -1e30f;
    float m = fmaxf(x0, x1);
#pragma unroll
    for (int o = 16; o > 0; o >>= 1) m = fmaxf(m, __shfl_xor_sync(0xffffffffu, m, o));
    float s = expf(x0 - m) + ((lane < 8) ? expf(x1 - m) : 0.f);
#pragma unroll
    for (int o = 16; o > 0; o >>= 1) s += __shfl_xor_sync(0xffffffffu, s, o);
    float l = m + logf(s);
    r[lane] = x0 - l;
    if (lane < 8) r[lane + 32] = x1 - l;
}

// ---------------- launch ----------------------------------------------------
extern "C" void kernel_launch(void* const* d_in, const int* in_sizes, int n_in,
                              void* d_out, int out_size) {
    const float* x       = (const float*)d_in[0];
    const int*   ei      = (const int*)  d_in[1];
    const float* att     = (const float*)d_in[2];
    const float* W_mlp   = (const float*)d_in[3];
    const float* b_mlp   = (const float*)d_in[4];
    const float* W_mlp2  = (const float*)d_in[5];
    const float* b_mlp2  = (const float*)d_in[6];
    const float* W_init  = (const float*)d_in[7];
    const float* b_init  = (const float*)d_in[8];
    const float* W_init2 = (const float*)d_in[9];
    const float* b_init2 = (const float*)d_in[10];
    const float* W_convs = (const float*)d_in[11];
    const float* b_convs = (const float*)d_in[12];
    const float* fc1_W   = (const float*)d_in[13];
    const float* fc1_b   = (const float*)d_in[14];
    float* out = (float*)d_out;

    float *Cp, *hp, *hw2p, *accp, *Sp, *Wp, *dinvp, *maskp;
    cudaGetSymbolAddress((void**)&Cp,    g_C);
    cudaGetSymbolAddress((void**)&hp,    g_h);
    cudaGetSymbolAddress((void**)&hw2p,  g_hw2);
    cudaGetSymbolAddress((void**)&accp,  g_acc);
    cudaGetSymbolAddress((void**)&Sp,    g_S);
    cudaGetSymbolAddress((void**)&Wp,    g_W);
    cudaGetSymbolAddress((void**)&dinvp, g_dinv);
    cudaGetSymbolAddress((void**)&maskp, g_mask);

    const int T = 256;
    const int n4b    = (NN * (DH / 4) + T - 1) / T;
    const int scat_b = (NE * 32 + T - 1) / T;
    const int Mt = (NN + 127) / 128;   // 391

    // launches 1-5 (so that launch #6, captured by ncu -s 5 -c 1, is the big GEMM)
    k_mask<<<1, 32>>>(att);
    k_fill1<<<(3 * NN + T - 1) / T, T>>>(dinvp, 3 * NN);
    k_deg<<<(3 * NE + T - 1) / T, T>>>(ei, dinvp);
    k_rsqrt<<<(3 * NN + T - 1) / T, T>>>(dinvp, 3 * NN);
    k_pack<<<(DIN * NC + T - 1) / T, T>>>(W_init, W_convs, W_mlp, Wp);

    // #6: packed X-side GEMM: g_C = X @ Wcat ; cols>=1024 get +b_mlp, relu
    gemm_tf32<true, true, false><<<dim3(NC / 128, Mt), T>>>(
        x, Wp, b_mlp, nullptr, Cp, NN, NC, DIN, DIN, NC, NC, 1024);

    // MLP branch: acc = relu(H1 @ W_mlp2 + b_mlp2) * mask[3]
    gemm_tf32<true, true, true><<<dim3(DH / 128, Mt), T>>>(
        Cp + 1024, W_mlp2, b_mlp2, maskp + 3, accp, NN, DH, DH, NC, DH, DH, 0);

    const int* src2 = ei + (2 * 2 + 0) * NE;
    const int* dst2 = ei + (2 * 2 + 1) * NE;

    // init branch hop 1: g_h = relu(gcn(x, W_init, g2))
    k_selfloop<<<n4b, T>>>(Cp, NC, dinvp + 2 * NN, Sp);
    k_scatter<<<scat_b, T>>>(src2, dst2, dinvp + 2 * NN, Cp, NC, Sp);
    k_post<false><<<n4b, T>>>(Sp, b_init, nullptr, hp);

    // hop 2: acc += relu(gcn(g_h, W_init2, g2)) * mask[4]
    gemm_tf32<false, false, false><<<dim3(DH / 128, Mt), T>>>(
        hp, W_init2, nullptr, nullptr, hw2p, NN, DH, DH, DH, DH, DH, 0);
    k_selfloop<<<n4b, T>>>(hw2p, DH, dinvp + 2 * NN, Sp);
    k_scatter<<<scat_b, T>>>(src2, dst2, dinvp + 2 * NN, hw2p, DH, Sp);
    k_post<true><<<n4b, T>>>(Sp, b_init2, maskp + 4, accp);

    // conv layers: acc += relu(gcn(x, W_convs[i], g_i)) * mask[i]
    for (int i = 0; i < 3; i++) {
        const int* s = ei + (i * 2 + 0) * NE;
        const int* d = ei + (i * 2 + 1) * NE;
        const float* slice = Cp + (1 + i) * 256;
        k_selfloop<<<n4b, T>>>(slice, NC, dinvp + i * NN, Sp);
        k_scatter<<<scat_b, T>>>(s, d, dinvp + i * NN, slice, NC, Sp);
        k_post<true><<<n4b, T>>>(Sp, b_convs + (size_t)i * DH, maskp + i, accp);
    }

    // logits + log-softmax
    gemm_tf32<true, false, false><<<dim3(1, Mt), T>>>(
        accp, fc1_W, fc1_b, nullptr, out, NN, DOUT, DH, DH, DOUT, DOUT, 0);
    k_lsm<<<(NN + 7) / 8, 256>>>(out, NN);
}

// round 4
// speedup vs baseline: 5.1397x; 2.9990x over previous
#include <cuda_runtime.h>
#include <math.h>
#include <stdint.h>

#define NN   50000
#define NE   800000
#define DIN  500
#define DH   256
#define NC   1280     // packed columns: [W_init | W_conv0 | W_conv1 | W_conv2 | W_mlp]
#define DOUT 40

// ---------------- scratch (static device globals: allocation-free) ----------
__device__ float g_C[(size_t)NN * NC];   // packed X-side GEMM outputs (256 MB)
__device__ float g_h[NN * DH];           // hop-1 output of init branch
__device__ float g_hw2[NN * DH];         // hop-2 hw
__device__ float g_acc[NN * DH];
__device__ float g_W[DIN * NC];          // packed weights
__device__ float g_dinv[3 * NN];
__device__ int   g_cnt[3 * NN];
__device__ int   g_cursor[3 * NN];
__device__ int   g_rowptr[3 * (NN + 1)];
__device__ int   g_colidx[3 * NE];
__device__ float g_mask[8];

// ---------------- prep kernels ----------------------------------------------
__global__ void k_zero(int* __restrict__ a, int* __restrict__ b, int n) {
    int i = blockIdx.x * blockDim.x + threadIdx.x;
    if (i < n) { a[i] = 0; b[i] = 0; }
}

__global__ void k_count(const int* __restrict__ ei, int* __restrict__ cnt) {
    int i = blockIdx.x * blockDim.x + threadIdx.x;
    if (i >= 3 * NE) return;
    int g = i / NE, e = i - g * NE;
    int d = ei[(g * 2 + 1) * NE + e];
    atomicAdd(&cnt[g * NN + d], 1);
}

// one block per graph: exclusive scan of counts -> rowptr; dinv = rsqrt(cnt+1)
__global__ void __launch_bounds__(1024)
k_scan(const int* __restrict__ cnt, int* __restrict__ rowptr, float* __restrict__ dinv) {
    int g = blockIdx.x;
    const int* c = cnt + g * NN;
    int* rp = rowptr + g * (NN + 1);
    __shared__ int wsum[32];
    __shared__ int carry;
    int tid = threadIdx.x, lane = tid & 31, wid = tid >> 5;
    if (tid == 0) { carry = 0; rp[0] = 0; }
    __syncthreads();
    for (int base = 0; base < NN; base += 1024) {
        int i = base + tid;
        int v = (i < NN) ? c[i] : 0;
        if (i < NN) dinv[g * NN + i] = rsqrtf((float)(v + 1));
        int s = v;
#pragma unroll
        for (int o = 1; o < 32; o <<= 1) {
            int t = __shfl_up_sync(0xffffffffu, s, o);
            if (lane >= o) s += t;
        }
        if (lane == 31) wsum[wid] = s;
        __syncthreads();
        if (wid == 0) {
            int t = wsum[lane];
#pragma unroll
            for (int o = 1; o < 32; o <<= 1) {
                int u = __shfl_up_sync(0xffffffffu, t, o);
                if (lane >= o) t += u;
            }
            wsum[lane] = t;
        }
        __syncthreads();
        int incl = s + (wid > 0 ? wsum[wid - 1] : 0) + carry;
        if (i < NN) rp[i + 1] = incl;
        __syncthreads();
        if (tid == 1023) carry = incl;
        __syncthreads();
    }
}

__global__ void k_fillcsr(const int* __restrict__ ei, const int* __restrict__ rowptr,
                          int* __restrict__ cursor, int* __restrict__ colidx) {
    int i = blockIdx.x * blockDim.x + threadIdx.x;
    if (i >= 3 * NE) return;
    int g = i / NE, e = i - g * NE;
    int s = ei[(g * 2 + 0) * NE + e];
    int d = ei[(g * 2 + 1) * NE + e];
    int pos = rowptr[g * (NN + 1) + d] + atomicAdd(&cursor[g * NN + d], 1);
    colidx[g * NE + pos] = s;
}

// pack weights: g_W[k][n], slice s=n/256 -> {W_init, W_conv0..2, W_mlp}
__global__ void k_pack(const float* __restrict__ Wi, const float* __restrict__ Wc,
                       const float* __restrict__ Wm, float* __restrict__ Wcat) {
    int i = blockIdx.x * blockDim.x + threadIdx.x;
    if (i >= DIN * NC) return;
    int k = i / NC, n = i - k * NC;
    int s = n >> 8, c = n & 255;
    float v;
    if (s == 0)      v = Wi[k * DH + c];
    else if (s <= 3) v = Wc[(size_t)(s - 1) * DIN * DH + k * DH + c];
    else             v = Wm[k * DH + c];
    Wcat[i] = v;
}

__global__ void k_mask(const float* __restrict__ att) {
    if (threadIdx.x == 0) {
        float m = -1e30f;
        for (int i = 0; i < 5; i++) m = fmaxf(m, att[i]);
        float e[5], s = 0.f;
        for (int i = 0; i < 5; i++) { e[i] = expf(att[i] - m); s += e[i]; }
        for (int i = 0; i < 5; i++) g_mask[i] = e[i] / s;
    }
}

// ---------------- fused GCN aggregation (gather-side, no atomics) -----------
// warp per node v: agg = dinv[v]^2*hw[v] + sum_e dinv[src]*dinv[v]*hw[src]
// epilogue: ACCUM ? out[v] += relu(agg+bias)*mask : out[v] = relu(agg+bias)
template <bool ACCUM>
__global__ void __launch_bounds__(256)
k_agg(const int* __restrict__ rowptr, const int* __restrict__ colidx,
      const float* __restrict__ dinv, const float* __restrict__ hw, int ldh,
      const float* __restrict__ bias, const float* __restrict__ maskPtr,
      float* __restrict__ out) {
    int v = blockIdx.x * 8 + (threadIdx.x >> 5);
    if (v >= NN) return;
    int lane = threadIdx.x & 31;
    float dv = dinv[v];
    int e0 = rowptr[v], e1 = rowptr[v + 1];

    const float4* hv = (const float4*)(hw + (size_t)v * ldh);
    float wsl = dv * dv;
    float4 x0 = hv[lane], x1 = hv[lane + 32];
    float4 a0 = make_float4(x0.x * wsl, x0.y * wsl, x0.z * wsl, x0.w * wsl);
    float4 a1 = make_float4(x1.x * wsl, x1.y * wsl, x1.z * wsl, x1.w * wsl);

    for (int base = e0; base < e1; base += 32) {
        int idx = base + lane;
        int mysrc = 0; float myw = 0.f;
        if (idx < e1) { mysrc = colidx[idx]; myw = dinv[mysrc] * dv; }
        int n = min(32, e1 - base);
        for (int j = 0; j < n; j++) {
            int s  = __shfl_sync(0xffffffffu, mysrc, j);
            float w = __shfl_sync(0xffffffffu, myw, j);
            const float4* h = (const float4*)(hw + (size_t)s * ldh);
            float4 v0 = h[lane], v1 = h[lane + 32];
            a0.x += v0.x * w; a0.y += v0.y * w; a0.z += v0.z * w; a0.w += v0.w * w;
            a1.x += v1.x * w; a1.y += v1.y * w; a1.z += v1.z * w; a1.w += v1.w * w;
        }
    }

    float4 b0 = ((const float4*)bias)[lane];
    float4 b1 = ((const float4*)bias)[lane + 32];
    a0.x = fmaxf(a0.x + b0.x, 0.f); a0.y = fmaxf(a0.y + b0.y, 0.f);
    a0.z = fmaxf(a0.z + b0.z, 0.f); a0.w = fmaxf(a0.w + b0.w, 0.f);
    a1.x = fmaxf(a1.x + b1.x, 0.f); a1.y = fmaxf(a1.y + b1.y, 0.f);
    a1.z = fmaxf(a1.z + b1.z, 0.f); a1.w = fmaxf(a1.w + b1.w, 0.f);

    float4* ov = (float4*)(out + (size_t)v * DH);
    if (ACCUM) {
        float m = *maskPtr;
        float4 o0 = ov[lane], o1 = ov[lane + 32];
        o0.x += a0.x * m; o0.y += a0.y * m; o0.z += a0.z * m; o0.w += a0.w * m;
        o1.x += a1.x * m; o1.y += a1.y * m; o1.z += a1.z * m; o1.w += a1.w * m;
        ov[lane] = o0; ov[lane + 32] = o1;
    } else {
        ov[lane] = a0; ov[lane + 32] = a1;
    }
}

// ---------------- tf32 tensor-core GEMM -------------------------------------
__device__ __forceinline__ uint32_t f2tf(float f) {
    uint32_t u; asm("cvt.rna.tf32.f32 %0, %1;" : "=r"(u) : "f"(f)); return u;
}
__device__ __forceinline__ void cpa16(uint32_t dst, const void* src, bool pred) {
    int sz = pred ? 16 : 0;
    asm volatile("cp.async.cg.shared.global [%0], [%1], 16, %2;\n"
                 :: "r"(dst), "l"(src), "r"(sz));
}

#define AS_STRIDE 20
#define BS_STRIDE 136

template <bool BIAS, bool RELU, bool SCALE>
__global__ void __launch_bounds__(256, 2)
gemm_tf32(const float* __restrict__ A, const float* __restrict__ B,
          const float* __restrict__ bias, const float* __restrict__ scalePtr,
          float* __restrict__ C, int M, int N, int K,
          int lda, int ldb, int ldc, int col0) {
    __shared__ float As[2][128 * AS_STRIDE];
    __shared__ float Bs[2][16 * BS_STRIDE];

    const int tid  = threadIdx.x;
    const int bm   = blockIdx.y * 128;
    const int bn   = blockIdx.x * 128;
    const int wid  = tid >> 5, lane = tid & 31;
    const int wm   = (wid >> 1) * 32;
    const int wn   = (wid & 1) * 64;
    const int g    = lane >> 2, q = lane & 3;

    float4 acc[2][8];
#pragma unroll
    for (int i = 0; i < 2; i++)
#pragma unroll
        for (int j = 0; j < 8; j++) acc[i][j] = make_float4(0.f, 0.f, 0.f, 0.f);

    const uint32_t sA = (uint32_t)__cvta_generic_to_shared(&As[0][0]);
    const uint32_t sB = (uint32_t)__cvta_generic_to_shared(&Bs[0][0]);
    const uint32_t aBufSz = 128 * AS_STRIDE * 4;
    const uint32_t bBufSz = 16 * BS_STRIDE * 4;

    const int T = (K + 15) / 16;

    auto load_tile = [&](int t, int buf) {
        int k0 = t * 16;
#pragma unroll
        for (int i = 0; i < 2; i++) {
            int c = tid + i * 256;
            int m = c >> 2, k = (c & 3) * 4;
            const float* srcp = A + (size_t)(bm + m) * lda + k0 + k;
            bool p = (bm + m < M) && (k0 + k < K);
            cpa16(sA + buf * aBufSz + (uint32_t)(m * AS_STRIDE + k) * 4, srcp, p);
        }
#pragma unroll
        for (int i = 0; i < 2; i++) {
            int c = tid + i * 256;
            int kk = c >> 5, n = (c & 31) * 4;
            const float* srcp = B + (size_t)(k0 + kk) * ldb + bn + n;
            bool p = (k0 + kk < K) && (bn + n < N);
            cpa16(sB + buf * bBufSz + (uint32_t)(kk * BS_STRIDE + n) * 4, srcp, p);
        }
    };

    load_tile(0, 0);
    asm volatile("cp.async.commit_group;\n" ::);

    for (int t = 0; t < T; t++) {
        if (t + 1 < T) {
            load_tile(t + 1, (t + 1) & 1);
            asm volatile("cp.async.commit_group;\n" ::);
            asm volatile("cp.async.wait_group 1;\n" ::);
        } else {
            asm volatile("cp.async.wait_group 0;\n" ::);
        }
        __syncthreads();

        const float* as = As[t & 1];
        const float* bs = Bs[t & 1];
#pragma unroll
        for (int kp = 0; kp < 2; kp++) {
            const int kb = kp * 8;
            uint32_t a[2][4], b[8][2];
#pragma unroll
            for (int i = 0; i < 2; i++) {
                int m0 = wm + i * 16;
                a[i][0] = f2tf(as[(m0 + g) * AS_STRIDE + kb + q]);
                a[i][1] = f2tf(as[(m0 + g + 8) * AS_STRIDE + kb + q]);
                a[i][2] = f2tf(as[(m0 + g) * AS_STRIDE + kb + q + 4]);
                a[i][3] = f2tf(as[(m0 + g + 8) * AS_STRIDE + kb + q + 4]);
            }
#pragma unroll
            for (int j = 0; j < 8; j++) {
                int n0 = wn + j * 8;
                b[j][0] = f2tf(bs[(kb + q) * BS_STRIDE + n0 + g]);
                b[j][1] = f2tf(bs[(kb + q + 4) * BS_STRIDE + n0 + g]);
            }
#pragma unroll
            for (int i = 0; i < 2; i++)
#pragma unroll
                for (int j = 0; j < 8; j++) {
                    asm volatile(
                        "mma.sync.aligned.m16n8k8.row.col.f32.tf32.tf32.f32 "
                        "{%0,%1,%2,%3},{%4,%5,%6,%7},{%8,%9},{%0,%1,%2,%3};"
                        : "+f"(acc[i][j].x), "+f"(acc[i][j].y),
                          "+f"(acc[i][j].z), "+f"(acc[i][j].w)
                        : "r"(a[i][0]), "r"(a[i][1]), "r"(a[i][2]), "r"(a[i][3]),
                          "r"(b[j][0]), "r"(b[j][1]));
                }
        }
        __syncthreads();
    }

    float scale = SCALE ? *scalePtr : 1.f;
#pragma unroll
    for (int i = 0; i < 2; i++) {
#pragma unroll
        for (int j = 0; j < 8; j++) {
            int col = bn + wn + j * 8 + q * 2;
            if (col >= N) continue;
            bool ep = (col >= col0);
            float b0 = 0.f, b1 = 0.f;
            if (BIAS && ep) { b0 = bias[col - col0]; b1 = bias[col + 1 - col0]; }
            int r0 = bm + wm + i * 16 + g;
            int r1 = r0 + 8;
            float v0 = acc[i][j].x, v1 = acc[i][j].y;
            float v2 = acc[i][j].z, v3 = acc[i][j].w;
            if (BIAS && ep) { v0 += b0; v1 += b1; v2 += b0; v3 += b1; }
            if (RELU && ep) {
                v0 = fmaxf(v0, 0.f); v1 = fmaxf(v1, 0.f);
                v2 = fmaxf(v2, 0.f); v3 = fmaxf(v3, 0.f);
            }
            if (SCALE) { v0 *= scale; v1 *= scale; v2 *= scale; v3 *= scale; }
            if (r0 < M) *(float2*)(C + (size_t)r0 * ldc + col) = make_float2(v0, v1);
            if (r1 < M) *(float2*)(C + (size_t)r1 * ldc + col) = make_float2(v2, v3);
        }
    }
}

// ---------------- in-place log-softmax over rows of 40 ----------------------
__global__ void k_lsm(float* __restrict__ p, int M) {
    int row = blockIdx.x * 8 + (threadIdx.x >> 5);
    int lane = threadIdx.x & 31;
    if (row >= M) return;
    float* r = p + (size_t)row * DOUT;
    float x0 = r[lane];
    float x1 = (lane < 8) ? r[lane + 32] : -1e30f;
    float m = fmaxf(x0, x1);
#pragma unroll
    for (int o = 16; o > 0; o >>= 1) m = fmaxf(m, __shfl_xor_sync(0xffffffffu, m, o));
    float s = expf(x0 - m) + ((lane < 8) ? expf(x1 - m) : 0.f);
#pragma unroll
    for (int o = 16; o > 0; o >>= 1) s += __shfl_xor_sync(0xffffffffu, s, o);
    float l = m + logf(s);
    r[lane] = x0 - l;
    if (lane < 8) r[lane + 32] = x1 - l;
}

// ---------------- launch ----------------------------------------------------
extern "C" void kernel_launch(void* const* d_in, const int* in_sizes, int n_in,
                              void* d_out, int out_size) {
    const float* x       = (const float*)d_in[0];
    const int*   ei      = (const int*)  d_in[1];
    const float* att     = (const float*)d_in[2];
    const float* W_mlp   = (const float*)d_in[3];
    const float* b_mlp   = (const float*)d_in[4];
    const float* W_mlp2  = (const float*)d_in[5];
    const float* b_mlp2  = (const float*)d_in[6];
    const float* W_init  = (const float*)d_in[7];
    const float* b_init  = (const float*)d_in[8];
    const float* W_init2 = (const float*)d_in[9];
    const float* b_init2 = (const float*)d_in[10];
    const float* W_convs = (const float*)d_in[11];
    const float* b_convs = (const float*)d_in[12];
    const float* fc1_W   = (const float*)d_in[13];
    const float* fc1_b   = (const float*)d_in[14];
    float* out = (float*)d_out;

    float *Cp, *hp, *hw2p, *accp, *Wp, *dinvp, *maskp;
    int *cntp, *curp, *rpp, *cip;
    cudaGetSymbolAddress((void**)&Cp,    g_C);
    cudaGetSymbolAddress((void**)&hp,    g_h);
    cudaGetSymbolAddress((void**)&hw2p,  g_hw2);
    cudaGetSymbolAddress((void**)&accp,  g_acc);
    cudaGetSymbolAddress((void**)&Wp,    g_W);
    cudaGetSymbolAddress((void**)&dinvp, g_dinv);
    cudaGetSymbolAddress((void**)&maskp, g_mask);
    cudaGetSymbolAddress((void**)&cntp,  g_cnt);
    cudaGetSymbolAddress((void**)&curp,  g_cursor);
    cudaGetSymbolAddress((void**)&rpp,   g_rowptr);
    cudaGetSymbolAddress((void**)&cip,   g_colidx);

    const int T = 256;
    const int Mt = (NN + 127) / 128;        // 391
    const int aggB = (NN + 7) / 8;          // 6250

    // CSR build (launches 1-4)
    k_zero<<<(3 * NN + T - 1) / T, T>>>(cntp, curp, 3 * NN);
    k_count<<<(3 * NE + T - 1) / T, T>>>(ei, cntp);
    k_scan<<<3, 1024>>>(cntp, rpp, dinvp);
    k_fillcsr<<<(3 * NE + T - 1) / T, T>>>(ei, rpp, curp, cip);
    // (5) weight pack
    k_pack<<<(DIN * NC + T - 1) / T, T>>>(W_init, W_convs, W_mlp, Wp);

    // (6) packed X-side GEMM: g_C = X @ Wcat ; cols>=1024 get +b_mlp, relu
    gemm_tf32<true, true, false><<<dim3(NC / 128, Mt), T>>>(
        x, Wp, b_mlp, nullptr, Cp, NN, NC, DIN, DIN, NC, NC, 1024);

    // (7) softmax mask
    k_mask<<<1, 32>>>(att);

    // (8) MLP branch initializes acc: acc = relu(H1 @ W_mlp2 + b_mlp2) * mask[3]
    gemm_tf32<true, true, true><<<dim3(DH / 128, Mt), T>>>(
        Cp + 1024, W_mlp2, b_mlp2, maskp + 3, accp, NN, DH, DH, NC, DH, DH, 0);

    const int* rp2 = rpp + 2 * (NN + 1);
    const int* ci2 = cip + 2 * NE;
    const float* dv2 = dinvp + 2 * NN;

    // (9) init hop 1: g_h = relu(gcn agg of g_C slice 0 over graph 2 + b_init)
    k_agg<false><<<aggB, T>>>(rp2, ci2, dv2, Cp, NC, b_init, nullptr, hp);

    // (10) hop-2 GEMM: hw2 = g_h @ W_init2
    gemm_tf32<false, false, false><<<dim3(DH / 128, Mt), T>>>(
        hp, W_init2, nullptr, nullptr, hw2p, NN, DH, DH, DH, DH, DH, 0);

    // (11) hop 2: acc += relu(agg(hw2, g2) + b_init2) * mask[4]
    k_agg<true><<<aggB, T>>>(rp2, ci2, dv2, hw2p, DH, b_init2, maskp + 4, accp);

    // (12-14) conv layers: acc += relu(agg(g_C slice 1+i, g_i) + b_convs[i]) * mask[i]
    for (int i = 0; i < 3; i++) {
        k_agg<true><<<aggB, T>>>(rpp + i * (NN + 1), cip + i * NE, dinvp + i * NN,
                                 Cp + (1 + i) * 256, NC,
                                 b_convs + (size_t)i * DH, maskp + i, accp);
    }

    // (15) logits, (16) log-softmax
    gemm_tf32<true, false, false><<<dim3(1, Mt), T>>>(
        accp, fc1_W, fc1_b, nullptr, out, NN, DOUT, DH, DH, DOUT, DOUT, 0);
    k_lsm<<<(NN + 7) / 8, 256>>>(out, NN);
}

// round 6
// speedup vs baseline: 6.5610x; 1.2765x over previous
#include <cuda_runtime.h>
#include <cuda_bf16.h>
#include <math.h>
#include <stdint.h>

#define NN   50000
#define NE   800000
#define DIN  500
#define KP   512      // K padded to multiple of 32
#define DH   256
#define NC   1280     // packed cols: [W_init | W_conv0 | W_conv1 | W_conv2 | W_mlp]
#define DOUT 40

typedef __nv_bfloat16  bf16;
typedef __nv_bfloat162 bf162;

// ---------------- scratch (static device globals) ---------------------------
__device__ bf16  g_Xb[(size_t)NN * KP];    // x in bf16, K-padded (51 MB)
__device__ bf16  g_C[(size_t)NN * NC];     // packed GEMM outputs (128 MB)
__device__ bf16  g_h[NN * DH];             // hop-1 output (bf16)
__device__ bf16  g_hw2[NN * DH];           // hop-2 hw (bf16)
__device__ float g_acc[NN * DH];           // fp32 accumulator
__device__ bf16  g_Wt[NC * KP];            // packed weights, TRANSPOSED [n][k]
__device__ bf16  g_W2t[DH * DH];           // W_init2^T
__device__ bf16  g_Wm2t[DH * DH];          // W_mlp2^T
__device__ float g_dinv[3 * NN];
__device__ int   g_cnt[3 * NN];
__device__ int   g_cursor[3 * NN];
__device__ int   g_rowptr[3 * (NN + 1)];
__device__ int   g_colidx[3 * NE];
__device__ float g_mask[8];

// ---------------- prep kernels ----------------------------------------------
__global__ void k_zero(int* __restrict__ a, int* __restrict__ b, int n) {
    int i = blockIdx.x * blockDim.x + threadIdx.x;
    if (i < n) { a[i] = 0; b[i] = 0; }
}

__global__ void k_count(const int* __restrict__ ei, int* __restrict__ cnt) {
    int i = blockIdx.x * blockDim.x + threadIdx.x;
    if (i >= 3 * NE) return;
    int g = i / NE, e = i - g * NE;
    int d = ei[(g * 2 + 1) * NE + e];
    atomicAdd(&cnt[g * NN + d], 1);
}

// convert x -> bf16 (K-padded) and pack/transpose all weights to bf16
__global__ void k_prep(const float* __restrict__ x,  const float* __restrict__ Wi,
                       const float* __restrict__ Wc, const float* __restrict__ Wm,
                       const float* __restrict__ W2, const float* __restrict__ Wm2,
                       bf16* __restrict__ Xb, bf16* __restrict__ Wt,
                       bf16* __restrict__ W2t, bf16* __restrict__ Wm2t) {
    long long i = (long long)blockIdx.x * blockDim.x + threadIdx.x;
    const long long NX = (long long)NN * KP;
    const long long NW = (long long)NC * KP;
    const long long N2 = DH * DH;
    if (i < NX) {
        int row = (int)(i >> 9), k = (int)(i & 511);
        Xb[i] = __float2bfloat16(k < DIN ? x[(size_t)row * DIN + k] : 0.f);
    } else if (i < NX + NW) {
        long long j = i - NX;
        int n = (int)(j >> 9), k = (int)(j & 511);
        float v = 0.f;
        if (k < DIN) {
            int s = n >> 8, c = n & 255;
            if (s == 0)      v = Wi[k * DH + c];
            else if (s <= 3) v = Wc[(size_t)(s - 1) * DIN * DH + k * DH + c];
            else             v = Wm[k * DH + c];
        }
        Wt[j] = __float2bfloat16(v);
    } else if (i < NX + NW + N2) {
        int j = (int)(i - NX - NW);
        int n = j >> 8, k = j & 255;
        W2t[j] = __float2bfloat16(W2[k * DH + n]);
    } else if (i < NX + NW + 2 * N2) {
        int j = (int)(i - NX - NW - N2);
        int n = j >> 8, k = j & 255;
        Wm2t[j] = __float2bfloat16(Wm2[k * DH + n]);
    }
}

// one block per graph: exclusive scan of counts -> rowptr; dinv = rsqrt(cnt+1)
__global__ void __launch_bounds__(1024)
k_scan(const int* __restrict__ cnt, int* __restrict__ rowptr, float* __restrict__ dinv) {
    int g = blockIdx.x;
    const int* c = cnt + g * NN;
    int* rp = rowptr + g * (NN + 1);
    __shared__ int wsum[32];
    __shared__ int carry;
    int tid = threadIdx.x, lane = tid & 31, wid = tid >> 5;
    if (tid == 0) { carry = 0; rp[0] = 0; }
    __syncthreads();
    for (int base = 0; base < NN; base += 1024) {
        int i = base + tid;
        int v = (i < NN) ? c[i] : 0;
        if (i < NN) dinv[g * NN + i] = rsqrtf((float)(v + 1));
        int s = v;
#pragma unroll
        for (int o = 1; o < 32; o <<= 1) {
            int t = __shfl_up_sync(0xffffffffu, s, o);
            if (lane >= o) s += t;
        }
        if (lane == 31) wsum[wid] = s;
        __syncthreads();
        if (wid == 0) {
            int t = wsum[lane];
#pragma unroll
            for (int o = 1; o < 32; o <<= 1) {
                int u = __shfl_up_sync(0xffffffffu, t, o);
                if (lane >= o) t += u;
            }
            wsum[lane] = t;
        }
        __syncthreads();
        int incl = s + (wid > 0 ? wsum[wid - 1] : 0) + carry;
        if (i < NN) rp[i + 1] = incl;
        __syncthreads();
        if (tid == 1023) carry = incl;
        __syncthreads();
    }
}

__global__ void k_fillcsr(const int* __restrict__ ei, const int* __restrict__ rowptr,
                          int* __restrict__ cursor, int* __restrict__ colidx) {
    int i = blockIdx.x * blockDim.x + threadIdx.x;
    if (i >= 3 * NE) return;
    int g = i / NE, e = i - g * NE;
    int s = ei[(g * 2 + 0) * NE + e];
    int d = ei[(g * 2 + 1) * NE + e];
    int pos = rowptr[g * (NN + 1) + d] + atomicAdd(&cursor[g * NN + d], 1);
    colidx[g * NE + pos] = s;
}

__global__ void k_mask(const float* __restrict__ att) {
    if (threadIdx.x == 0) {
        float m = -1e30f;
        for (int i = 0; i < 5; i++) m = fmaxf(m, att[i]);
        float e[5], s = 0.f;
        for (int i = 0; i < 5; i++) { e[i] = expf(att[i] - m); s += e[i]; }
        for (int i = 0; i < 5; i++) g_mask[i] = e[i] / s;
    }
}

// ---------------- fused GCN aggregation (bf16 sources) ----------------------
// warp per node v: agg = dinv[v]^2*hw[v] + sum_e dinv[src]*dinv[v]*hw[src]
// !ACCUM: outB[v] = bf16(relu(agg+bias));  ACCUM: outF[v] += relu(agg+bias)*mask
template <bool ACCUM>
__global__ void __launch_bounds__(256)
k_agg(const int* __restrict__ rowptr, const int* __restrict__ colidx,
      const float* __restrict__ dinv, const bf16* __restrict__ hw, int ldh,
      const float* __restrict__ bias, const float* __restrict__ maskPtr,
      bf16* __restrict__ outB, float* __restrict__ outF) {
    int v = blockIdx.x * 8 + (threadIdx.x >> 5);
    if (v >= NN) return;
    int lane = threadIdx.x & 31;
    float dv = dinv[v];
    int e0 = rowptr[v], e1 = rowptr[v + 1];

    float a[8];
    {
        float wsl = dv * dv;
        uint4 raw = *(const uint4*)(hw + (size_t)v * ldh + lane * 8);
        const bf162* pr = (const bf162*)&raw;
#pragma unroll
        for (int t = 0; t < 4; t++) {
            float2 f = __bfloat1622float2(pr[t]);
            a[2 * t] = f.x * wsl; a[2 * t + 1] = f.y * wsl;
        }
    }

    for (int base = e0; base < e1; base += 32) {
        int idx = base + lane;
        int mysrc = 0; float myw = 0.f;
        if (idx < e1) { mysrc = colidx[idx]; myw = dinv[mysrc] * dv; }
        int n = min(32, e1 - base);
        for (int j = 0; j < n; j++) {
            int s  = __shfl_sync(0xffffffffu, mysrc, j);
            float w = __shfl_sync(0xffffffffu, myw, j);
            uint4 raw = *(const uint4*)(hw + (size_t)s * ldh + lane * 8);
            const bf162* pr = (const bf162*)&raw;
#pragma unroll
            for (int t = 0; t < 4; t++) {
                float2 f = __bfloat1622float2(pr[t]);
                a[2 * t]     += f.x * w;
                a[2 * t + 1] += f.y * w;
            }
        }
    }

    float4 b0 = *(const float4*)(bias + lane * 8);
    float4 b1 = *(const float4*)(bias + lane * 8 + 4);
    a[0] = fmaxf(a[0] + b0.x, 0.f); a[1] = fmaxf(a[1] + b0.y, 0.f);
    a[2] = fmaxf(a[2] + b0.z, 0.f); a[3] = fmaxf(a[3] + b0.w, 0.f);
    a[4] = fmaxf(a[4] + b1.x, 0.f); a[5] = fmaxf(a[5] + b1.y, 0.f);
    a[6] = fmaxf(a[6] + b1.z, 0.f); a[7] = fmaxf(a[7] + b1.w, 0.f);

    if (ACCUM) {
        float m = *maskPtr;
        float* o = outF + (size_t)v * DH + lane * 8;
        float4 o0 = *(float4*)o, o1 = *(float4*)(o + 4);
        o0.x += a[0] * m; o0.y += a[1] * m; o0.z += a[2] * m; o0.w += a[3] * m;
        o1.x += a[4] * m; o1.y += a[5] * m; o1.z += a[6] * m; o1.w += a[7] * m;
        *(float4*)o = o0; *(float4*)(o + 4) = o1;
    } else {
        uint4 pk;
        bf162* pp = (bf162*)&pk;
        pp[0] = __float22bfloat162_rn(make_float2(a[0], a[1]));
        pp[1] = __float22bfloat162_rn(make_float2(a[2], a[3]));
        pp[2] = __float22bfloat162_rn(make_float2(a[4], a[5]));
        pp[3] = __float22bfloat162_rn(make_float2(a[6], a[7]));
        *(uint4*)(outB + (size_t)v * DH + lane * 8) = pk;
    }
}

// ---------------- bf16 tensor-core GEMM -------------------------------------
// C[M,N] = A[M,K] @ B[K,N], A bf16 row-major [M,lda], Bt bf16 TRANSPOSED [N,ldbt]
// (k contiguous). K, N multiples of 32/128; A rows predicated.
// 128x128 tile, BK=32, 256 threads, warp tile 32x64, m16n8k16 bf16 mma.
// Epilogue (cols >= col0): +bias, relu; scale all; OUTBF: store bf16 else fp32.
__device__ __forceinline__ void cpa16(uint32_t dst, const void* src, bool pred) {
    int sz = pred ? 16 : 0;
    asm volatile("cp.async.cg.shared.global [%0], [%1], 16, %2;\n"
                 :: "r"(dst), "l"(src), "r"(sz));
}

__device__ __forceinline__ uint32_t pack_bf2(float lo, float hi) {
    bf162 t = __float22bfloat162_rn(make_float2(lo, hi));
    uint32_t u;
    u = *reinterpret_cast<uint32_t*>(&t);
    return u;
}

#define STQ 40   // smem k-stride in halves (80B rows -> conflict-free)

template <bool BIAS, bool RELU, bool SCALE, bool OUTBF>
__global__ void __launch_bounds__(256, 2)
gemm_bf16(const bf16* __restrict__ A, const bf16* __restrict__ Bt,
          const float* __restrict__ bias, const float* __restrict__ scalePtr,
          void* __restrict__ Cv, int M, int N, int K,
          int lda, int ldbt, int ldc, int col0) {
    __shared__ bf16 As[2][128 * STQ];
    __shared__ bf16 Bs[2][128 * STQ];

    const int tid = threadIdx.x;
    const int bm  = blockIdx.y * 128;
    const int bn  = blockIdx.x * 128;
    const int wid = tid >> 5, lane = tid & 31;
    const int wm  = (wid >> 1) * 32;
    const int wn  = (wid & 1) * 64;
    const int g   = lane >> 2, q = lane & 3;

    float4 acc[2][8];
#pragma unroll
    for (int i = 0; i < 2; i++)
#pragma unroll
        for (int j = 0; j < 8; j++) acc[i][j] = make_float4(0.f, 0.f, 0.f, 0.f);

    const uint32_t sA = (uint32_t)__cvta_generic_to_shared(&As[0][0]);
    const uint32_t sB = (uint32_t)__cvta_generic_to_shared(&Bs[0][0]);
    const uint32_t bufSz = 128 * STQ * 2;

    const int T = K / 32;

    auto load_tile = [&](int t, int buf) {
        int k0 = t * 32;
#pragma unroll
        for (int i = 0; i < 2; i++) {
            int c = tid + i * 256;
            int row = c >> 2, kx = (c & 3) * 8;
            const bf16* srcp = A + (size_t)(bm + row) * lda + k0 + kx;
            cpa16(sA + buf * bufSz + (uint32_t)(row * STQ + kx) * 2, srcp, bm + row < M);
        }
#pragma unroll
        for (int i = 0; i < 2; i++) {
            int c = tid + i * 256;
            int row = c >> 2, kx = (c & 3) * 8;
            const bf16* srcp = Bt + (size_t)(bn + row) * ldbt + k0 + kx;
            cpa16(sB + buf * bufSz + (uint32_t)(row * STQ + kx) * 2, srcp, true);
        }
    };

    load_tile(0, 0);
    asm volatile("cp.async.commit_group;\n" ::);

    for (int t = 0; t < T; t++) {
        if (t + 1 < T) {
            load_tile(t + 1, (t + 1) & 1);
            asm volatile("cp.async.commit_group;\n" ::);
            asm volatile("cp.async.wait_group 1;\n" ::);
        } else {
            asm volatile("cp.async.wait_group 0;\n" ::);
        }
        __syncthreads();

        const bf16* as = As[t & 1];
        const bf16* bs = Bs[t & 1];
#pragma unroll
        for (int kp = 0; kp < 2; kp++) {
            const int kb = kp * 16;
            uint32_t a[2][4], b[8][2];
#pragma unroll
            for (int i = 0; i < 2; i++) {
                int r0 = (wm + i * 16 + g) * STQ;
                a[i][0] = *(const uint32_t*)&as[r0 + kb + 2 * q];
                a[i][1] = *(const uint32_t*)&as[r0 + 8 * STQ + kb + 2 * q];
                a[i][2] = *(const uint32_t*)&as[r0 + kb + 2 * q + 8];
                a[i][3] = *(const uint32_t*)&as[r0 + 8 * STQ + kb + 2 * q + 8];
            }
#pragma unroll
            for (int j = 0; j < 8; j++) {
                int rb = (wn + j * 8 + g) * STQ;
                b[j][0] = *(const uint32_t*)&bs[rb + kb + 2 * q];
                b[j][1] = *(const uint32_t*)&bs[rb + kb + 2 * q + 8];
            }
#pragma unroll
            for (int i = 0; i < 2; i++)
#pragma unroll
                for (int j = 0; j < 8; j++) {
                    asm volatile(
                        "mma.sync.aligned.m16n8k16.row.col.f32.bf16.bf16.f32 "
                        "{%0,%1,%2,%3},{%4,%5,%6,%7},{%8,%9},{%0,%1,%2,%3};"
                        : "+f"(acc[i][j].x), "+f"(acc[i][j].y),
                          "+f"(acc[i][j].z), "+f"(acc[i][j].w)
                        : "r"(a[i][0]), "r"(a[i][1]), "r"(a[i][2]), "r"(a[i][3]),
                          "r"(b[j][0]), "r"(b[j][1]));
                }
        }
        __syncthreads();
    }

    float scale = SCALE ? *scalePtr : 1.f;
#pragma unroll
    for (int i = 0; i < 2; i++) {
#pragma unroll
        for (int j = 0; j < 8; j++) {
            int col = bn + wn + j * 8 + q * 2;
            bool ep = (col >= col0);
            float b0 = 0.f, b1 = 0.f;
            if (BIAS && ep) { b0 = bias[col - col0]; b1 = bias[col + 1 - col0]; }
            int r0 = bm + wm + i * 16 + g;
            int r1 = r0 + 8;
            float v0 = acc[i][j].x, v1 = acc[i][j].y;
            float v2 = acc[i][j].z, v3 = acc[i][j].w;
            if (BIAS && ep) { v0 += b0; v1 += b1; v2 += b0; v3 += b1; }
            if (RELU && ep) {
                v0 = fmaxf(v0, 0.f); v1 = fmaxf(v1, 0.f);
                v2 = fmaxf(v2, 0.f); v3 = fmaxf(v3, 0.f);
            }
            if (SCALE) { v0 *= scale; v1 *= scale; v2 *= scale; v3 *= scale; }
            if (OUTBF) {
                bf16* C = (bf16*)Cv;
                if (r0 < M) *(uint32_t*)(C + (size_t)r0 * ldc + col) = pack_bf2(v0, v1);
                if (r1 < M) *(uint32_t*)(C + (size_t)r1 * ldc + col) = pack_bf2(v2, v3);
            } else {
                float* C = (float*)Cv;
                if (r0 < M) *(float2*)(C + (size_t)r0 * ldc + col) = make_float2(v0, v1);
                if (r1 < M) *(float2*)(C + (size_t)r1 * ldc + col) = make_float2(v2, v3);
            }
        }
    }
}

// ---------------- tf32 GEMM (kept for fc1: fp32 A/B) ------------------------
__device__ __forceinline__ uint32_t f2tf(float f) {
    uint32_t u; asm("cvt.rna.tf32.f32 %0, %1;" : "=r"(u) : "f"(f)); return u;
}
#define AS_STRIDE 20
#define BS_STRIDE 136

__global__ void __launch_bounds__(256, 2)
gemm_fc1(const float* __restrict__ A, const float* __restrict__ B,
         const float* __restrict__ bias, float* __restrict__ C,
         int M, int N, int K, int lda, int ldb, int ldc) {
    __shared__ float As2[2][128 * AS_STRIDE];
    __shared__ float Bs2[2][16 * BS_STRIDE];

    const int tid = threadIdx.x;
    const int bm  = blockIdx.y * 128;
    const int bn  = 0;
    const int wid = tid >> 5, lane = tid & 31;
    const int wm  = (wid >> 1) * 32;
    const int wn  = (wid & 1) * 64;
    const int g   = lane >> 2, q = lane & 3;

    float4 acc[2][8];
#pragma unroll
    for (int i = 0; i < 2; i++)
#pragma unroll
        for (int j = 0; j < 8; j++) acc[i][j] = make_float4(0.f, 0.f, 0.f, 0.f);

    const uint32_t sA = (uint32_t)__cvta_generic_to_shared(&As2[0][0]);
    const uint32_t sB = (uint32_t)__cvta_generic_to_shared(&Bs2[0][0]);
    const uint32_t aBufSz = 128 * AS_STRIDE * 4;
    const uint32_t bBufSz = 16 * BS_STRIDE * 4;
    const int T = (K + 15) / 16;

    auto load_tile = [&](int t, int buf) {
        int k0 = t * 16;
#pragma unroll
        for (int i = 0; i < 2; i++) {
            int c = tid + i * 256;
            int m = c >> 2, k = (c & 3) * 4;
            const float* srcp = A + (size_t)(bm + m) * lda + k0 + k;
            bool p = (bm + m < M) && (k0 + k < K);
            cpa16(sA + buf * aBufSz + (uint32_t)(m * AS_STRIDE + k) * 4, srcp, p);
        }
#pragma unroll
        for (int i = 0; i < 2; i++) {
            int c = tid + i * 256;
            int kk = c >> 5, n = (c & 31) * 4;
            const float* srcp = B + (size_t)(k0 + kk) * ldb + bn + n;
            bool p = (k0 + kk < K) && (bn + n < N);
            cpa16(sB + buf * bBufSz + (uint32_t)(kk * BS_STRIDE + n) * 4, srcp, p);
        }
    };

    load_tile(0, 0);
    asm volatile("cp.async.commit_group;\n" ::);

    for (int t = 0; t < T; t++) {
        if (t + 1 < T) {
            load_tile(t + 1, (t + 1) & 1);
            asm volatile("cp.async.commit_group;\n" ::);
            asm volatile("cp.async.wait_group 1;\n" ::);
        } else {
            asm volatile("cp.async.wait_group 0;\n" ::);
        }
        __syncthreads();
        const float* as = As2[t & 1];
        const float* bs = Bs2[t & 1];
#pragma unroll
        for (int kp = 0; kp < 2; kp++) {
            const int kb = kp * 8;
            uint32_t a[2][4], b[8][2];
#pragma unroll
            for (int i = 0; i < 2; i++) {
                int m0 = wm + i * 16;
                a[i][0] = f2tf(as[(m0 + g) * AS_STRIDE + kb + q]);
                a[i][1] = f2tf(as[(m0 + g + 8) * AS_STRIDE + kb + q]);
                a[i][2] = f2tf(as[(m0 + g) * AS_STRIDE + kb + q + 4]);
                a[i][3] = f2tf(as[(m0 + g + 8) * AS_STRIDE + kb + q + 4]);
            }
#pragma unroll
            for (int j = 0; j < 8; j++) {
                int n0 = wn + j * 8;
                b[j][0] = f2tf(bs[(kb + q) * BS_STRIDE + n0 + g]);
                b[j][1] = f2tf(bs[(kb + q + 4) * BS_STRIDE + n0 + g]);
            }
#pragma unroll
            for (int i = 0; i < 2; i++)
#pragma unroll
                for (int j = 0; j < 8; j++) {
                    asm volatile(
                        "mma.sync.aligned.m16n8k8.row.col.f32.tf32.tf32.f32 "
                        "{%0,%1,%2,%3},{%4,%5,%6,%7},{%8,%9},{%0,%1,%2,%3};"
                        : "+f"(acc[i][j].x), "+f"(acc[i][j].y),
                          "+f"(acc[i][j].z), "+f"(acc[i][j].w)
                        : "r"(a[i][0]), "r"(a[i][1]), "r"(a[i][2]), "r"(a[i][3]),
                          "r"(b[j][0]), "r"(b[j][1]));
                }
        }
        __syncthreads();
    }

#pragma unroll
    for (int i = 0; i < 2; i++) {
#pragma unroll
        for (int j = 0; j < 8; j++) {
            int col = bn + wn + j * 8 + q * 2;
            if (col >= N) continue;
            float b0 = bias[col], b1 = bias[col + 1];
            int r0 = bm + wm + i * 16 + g;
            int r1 = r0 + 8;
            if (r0 < M) *(float2*)(C + (size_t)r0 * ldc + col) =
                make_float2(acc[i][j].x + b0, acc[i][j].y + b1);
            if (r1 < M) *(float2*)(C + (size_t)r1 * ldc + col) =
                make_float2(acc[i][j].z + b0, acc[i][j].w + b1);
        }
    }
}

// ---------------- in-place log-softmax over rows of 40 ----------------------
__global__ void k_lsm(float* __restrict__ p, int M) {
    int row = blockIdx.x * 8 + (threadIdx.x >> 5);
    int lane = threadIdx.x & 31;
    if (row >= M) return;
    float* r = p + (size_t)row * DOUT;
    float x0 = r[lane];
    float x1 = (lane < 8) ? r[lane + 32] : -1e30f;
    float m = fmaxf(x0, x1);
#pragma unroll
    for (int o = 16; o > 0; o >>= 1) m = fmaxf(m, __shfl_xor_sync(0xffffffffu, m, o));
    float s = expf(x0 - m) + ((lane < 8) ? expf(x1 - m) : 0.f);
#pragma unroll
    for (int o = 16; o > 0; o >>= 1) s += __shfl_xor_sync(0xffffffffu, s, o);
    float l = m + logf(s);
    r[lane] = x0 - l;
    if (lane < 8) r[lane + 32] = x1 - l;
}

// ---------------- launch ----------------------------------------------------
extern "C" void kernel_launch(void* const* d_in, const int* in_sizes, int n_in,
                              void* d_out, int out_size) {
    const float* x       = (const float*)d_in[0];
    const int*   ei      = (const int*)  d_in[1];
    const float* att     = (const float*)d_in[2];
    const float* W_mlp   = (const float*)d_in[3];
    const float* b_mlp   = (const float*)d_in[4];
    const float* W_mlp2  = (const float*)d_in[5];
    const float* b_mlp2  = (const float*)d_in[6];
    const float* W_init  = (const float*)d_in[7];
    const float* b_init  = (const float*)d_in[8];
    const float* W_init2 = (const float*)d_in[9];
    const float* b_init2 = (const float*)d_in[10];
    const float* W_convs = (const float*)d_in[11];
    const float* b_convs = (const float*)d_in[12];
    const float* fc1_W   = (const float*)d_in[13];
    const float* fc1_b   = (const float*)d_in[14];
    float* out = (float*)d_out;

    bf16 *Xbp, *Cp, *hp, *hw2p, *Wtp, *W2tp, *Wm2tp;
    float *accp, *dinvp, *maskp;
    int *cntp, *curp, *rpp, *cip;
    cudaGetSymbolAddress((void**)&Xbp,   g_Xb);
    cudaGetSymbolAddress((void**)&Cp,    g_C);
    cudaGetSymbolAddress((void**)&hp,    g_h);
    cudaGetSymbolAddress((void**)&hw2p,  g_hw2);
    cudaGetSymbolAddress((void**)&accp,  g_acc);
    cudaGetSymbolAddress((void**)&Wtp,   g_Wt);
    cudaGetSymbolAddress((void**)&W2tp,  g_W2t);
    cudaGetSymbolAddress((void**)&Wm2tp, g_Wm2t);
    cudaGetSymbolAddress((void**)&dinvp, g_dinv);
    cudaGetSymbolAddress((void**)&maskp, g_mask);
    cudaGetSymbolAddress((void**)&cntp,  g_cnt);
    cudaGetSymbolAddress((void**)&curp,  g_cursor);
    cudaGetSymbolAddress((void**)&rpp,   g_rowptr);
    cudaGetSymbolAddress((void**)&cip,   g_colidx);

    const int T = 256;
    const int Mt = (NN + 127) / 128;
    const int aggB = (NN + 7) / 8;
    const long long prepN = (long long)NN * KP + (long long)NC * KP + 2LL * DH * DH;

    // (1)(2) CSR count phase
    k_zero<<<(3 * NN + T - 1) / T, T>>>(cntp, curp, 3 * NN);
    k_count<<<(3 * NE + T - 1) / T, T>>>(ei, cntp);
    // (3) dtype conversion + weight pack/transpose
    k_prep<<<(int)((prepN + T - 1) / T), T>>>(x, W_init, W_convs, W_mlp, W_init2, W_mlp2,
                                              Xbp, Wtp, W2tp, Wm2tp);
    // (4) big packed GEMM: g_C = Xb @ Wcat (bf16 out); cols>=1024: +b_mlp, relu
    gemm_bf16<true, true, false, true><<<dim3(NC / 128, Mt), T>>>(
        Xbp, Wtp, b_mlp, nullptr, Cp, NN, NC, KP, KP, KP, NC, 1024);
    // (5)(6) finish CSR
    k_scan<<<3, 1024>>>(cntp, rpp, dinvp);
    k_fillcsr<<<(3 * NE + T - 1) / T, T>>>(ei, rpp, curp, cip);
    // (7) softmax mask
    k_mask<<<1, 32>>>(att);

    // (8) MLP branch initializes acc: acc = relu(H1 @ W_mlp2 + b_mlp2) * mask[3]
    gemm_bf16<true, true, true, false><<<dim3(DH / 128, Mt), T>>>(
        Cp + 1024, Wm2tp, b_mlp2, maskp + 3, accp, NN, DH, DH, NC, DH, DH, 0);

    const int* rp2 = rpp + 2 * (NN + 1);
    const int* ci2 = cip + 2 * NE;
    const float* dv2 = dinvp + 2 * NN;

    // (9) init hop 1: g_h = relu(agg(g_C slice0, graph2) + b_init)  (bf16 out)
    k_agg<false><<<aggB, T>>>(rp2, ci2, dv2, Cp, NC, b_init, nullptr, hp, nullptr);
    // (10) hop2 GEMM: hw2 = g_h @ W_init2  (bf16 out)
    gemm_bf16<false, false, false, true><<<dim3(DH / 128, Mt), T>>>(
        hp, W2tp, nullptr, nullptr, hw2p, NN, DH, DH, DH, DH, DH, 0);
    // (11) hop 2: acc += relu(agg(hw2, graph2) + b_init2) * mask[4]
    k_agg<true><<<aggB, T>>>(rp2, ci2, dv2, hw2p, DH, b_init2, maskp + 4, nullptr, accp);
    // (12-14) conv layers
    for (int i = 0; i < 3; i++) {
        k_agg<true><<<aggB, T>>>(rpp + i * (NN + 1), cip + i * NE, dinvp + i * NN,
                                 Cp + (1 + i) * 256, NC,
                                 b_convs + (size_t)i * DH, maskp + i, nullptr, accp);
    }

    // (15) logits (tf32, fp32 acc), (16) log-softmax
    gemm_fc1<<<dim3(1, Mt), T>>>(accp, fc1_W, fc1_b, out, NN, DOUT, DH, DH, DOUT, DOUT);
    k_lsm<<<(NN + 7) / 8, 256>>>(out, NN);
}

// round 7
// speedup vs baseline: 7.1574x; 1.0909x over previous
#include <cuda_runtime.h>
#include <cuda_bf16.h>
#include <math.h>
#include <stdint.h>

#define NN   50000
#define NE   800000
#define DIN  500
#define KP   512      // K padded to multiple of 32
#define DH   256
#define NC   1280     // packed cols: [W_init | W_conv0 | W_conv1 | W_conv2 | W_mlp]
#define DOUT 40

typedef __nv_bfloat16  bf16;
typedef __nv_bfloat162 bf162;

// ---------------- scratch (static device globals) ---------------------------
__device__ bf16  g_Xb[(size_t)NN * KP];
__device__ bf16  g_C[(size_t)NN * NC];
__device__ bf16  g_h[NN * DH];
__device__ bf16  g_hw2[NN * DH];
__device__ float g_acc[NN * DH];
__device__ bf16  g_Wt[NC * KP];
__device__ bf16  g_W2t[DH * DH];
__device__ bf16  g_Wm2t[DH * DH];
__device__ float g_dinv[3 * NN];
__device__ int   g_cnt[3 * NN];
__device__ int   g_cursor[3 * NN];
__device__ int   g_rowptr[3 * (NN + 1)];
__device__ int   g_colidx[3 * NE];
__device__ float g_mask[8];

// ---------------- prep kernels ----------------------------------------------
__global__ void k_zero(int* __restrict__ a, int* __restrict__ b, int n) {
    int i = blockIdx.x * blockDim.x + threadIdx.x;
    if (i < n) { a[i] = 0; b[i] = 0; }
}

__global__ void k_count(const int* __restrict__ ei, int* __restrict__ cnt) {
    int i = blockIdx.x * blockDim.x + threadIdx.x;
    if (i >= 3 * NE) return;
    int g = i / NE, e = i - g * NE;
    int d = ei[(g * 2 + 1) * NE + e];
    atomicAdd(&cnt[g * NN + d], 1);
}

__global__ void k_prep(const float* __restrict__ x,  const float* __restrict__ Wi,
                       const float* __restrict__ Wc, const float* __restrict__ Wm,
                       const float* __restrict__ W2, const float* __restrict__ Wm2,
                       bf16* __restrict__ Xb, bf16* __restrict__ Wt,
                       bf16* __restrict__ W2t, bf16* __restrict__ Wm2t) {
    long long i = (long long)blockIdx.x * blockDim.x + threadIdx.x;
    const long long NX = (long long)NN * KP;
    const long long NW = (long long)NC * KP;
    const long long N2 = DH * DH;
    if (i < NX) {
        int row = (int)(i >> 9), k = (int)(i & 511);
        Xb[i] = __float2bfloat16(k < DIN ? x[(size_t)row * DIN + k] : 0.f);
    } else if (i < NX + NW) {
        long long j = i - NX;
        int n = (int)(j >> 9), k = (int)(j & 511);
        float v = 0.f;
        if (k < DIN) {
            int s = n >> 8, c = n & 255;
            if (s == 0)      v = Wi[k * DH + c];
            else if (s <= 3) v = Wc[(size_t)(s - 1) * DIN * DH + k * DH + c];
            else             v = Wm[k * DH + c];
        }
        Wt[j] = __float2bfloat16(v);
    } else if (i < NX + NW + N2) {
        int j = (int)(i - NX - NW);
        int n = j >> 8, k = j & 255;
        W2t[j] = __float2bfloat16(W2[k * DH + n]);
    } else if (i < NX + NW + 2 * N2) {
        int j = (int)(i - NX - NW - N2);
        int n = j >> 8, k = j & 255;
        Wm2t[j] = __float2bfloat16(Wm2[k * DH + n]);
    }
}

__global__ void __launch_bounds__(1024)
k_scan(const int* __restrict__ cnt, int* __restrict__ rowptr, float* __restrict__ dinv) {
    int g = blockIdx.x;
    const int* c = cnt + g * NN;
    int* rp = rowptr + g * (NN + 1);
    __shared__ int wsum[32];
    __shared__ int carry;
    int tid = threadIdx.x, lane = tid & 31, wid = tid >> 5;
    if (tid == 0) { carry = 0; rp[0] = 0; }
    __syncthreads();
    for (int base = 0; base < NN; base += 1024) {
        int i = base + tid;
        int v = (i < NN) ? c[i] : 0;
        if (i < NN) dinv[g * NN + i] = rsqrtf((float)(v + 1));
        int s = v;
#pragma unroll
        for (int o = 1; o < 32; o <<= 1) {
            int t = __shfl_up_sync(0xffffffffu, s, o);
            if (lane >= o) s += t;
        }
        if (lane == 31) wsum[wid] = s;
        __syncthreads();
        if (wid == 0) {
            int t = wsum[lane];
#pragma unroll
            for (int o = 1; o < 32; o <<= 1) {
                int u = __shfl_up_sync(0xffffffffu, t, o);
                if (lane >= o) t += u;
            }
            wsum[lane] = t;
        }
        __syncthreads();
        int incl = s + (wid > 0 ? wsum[wid - 1] : 0) + carry;
        if (i < NN) rp[i + 1] = incl;
        __syncthreads();
        if (tid == 1023) carry = incl;
        __syncthreads();
    }
}

__global__ void k_fillcsr(const int* __restrict__ ei, const int* __restrict__ rowptr,
                          int* __restrict__ cursor, int* __restrict__ colidx) {
    int i = blockIdx.x * blockDim.x + threadIdx.x;
    if (i >= 3 * NE) return;
    int g = i / NE, e = i - g * NE;
    int s = ei[(g * 2 + 0) * NE + e];
    int d = ei[(g * 2 + 1) * NE + e];
    int pos = rowptr[g * (NN + 1) + d] + atomicAdd(&cursor[g * NN + d], 1);
    colidx[g * NE + pos] = s;
}

__global__ void k_mask(const float* __restrict__ att) {
    if (threadIdx.x == 0) {
        float m = -1e30f;
        for (int i = 0; i < 5; i++) m = fmaxf(m, att[i]);
        float e[5], s = 0.f;
        for (int i = 0; i < 5; i++) { e[i] = expf(att[i] - m); s += e[i]; }
        for (int i = 0; i < 5; i++) g_mask[i] = e[i] / s;
    }
}

// ---------------- agg helpers ------------------------------------------------
__device__ __forceinline__ void acc8(float* a, uint4 raw, float w) {
    const bf162* pr = (const bf162*)&raw;
#pragma unroll
    for (int t = 0; t < 4; t++) {
        float2 f = __bfloat1622float2(pr[t]);
        a[2 * t]     += f.x * w;
        a[2 * t + 1] += f.y * w;
    }
}

// ---------------- fused GCN aggregation (bf16 sources, unroll-4) ------------
template <bool ACCUM>
__global__ void __launch_bounds__(256)
k_agg(const int* __restrict__ rowptr, const int* __restrict__ colidx,
      const float* __restrict__ dinv, const bf16* __restrict__ hw, int ldh,
      const float* __restrict__ bias, const float* __restrict__ maskPtr,
      bf16* __restrict__ outB, float* __restrict__ outF) {
    int v = blockIdx.x * 8 + (threadIdx.x >> 5);
    if (v >= NN) return;
    int lane = threadIdx.x & 31;
    float dv = dinv[v];
    int e0 = rowptr[v], e1 = rowptr[v + 1];

    float a[8];
    {
        float wsl = dv * dv;
        uint4 raw = *(const uint4*)(hw + (size_t)v * ldh + lane * 8);
        const bf162* pr = (const bf162*)&raw;
#pragma unroll
        for (int t = 0; t < 4; t++) {
            float2 f = __bfloat1622float2(pr[t]);
            a[2 * t] = f.x * wsl; a[2 * t + 1] = f.y * wsl;
        }
    }

    for (int base = e0; base < e1; base += 32) {
        int idx = base + lane;
        int mysrc = 0; float myw = 0.f;
        if (idx < e1) { mysrc = colidx[idx]; myw = dinv[mysrc] * dv; }
        int n = min(32, e1 - base);
        int j = 0;
        for (; j + 3 < n; j += 4) {
            int s0 = __shfl_sync(0xffffffffu, mysrc, j);
            int s1 = __shfl_sync(0xffffffffu, mysrc, j + 1);
            int s2 = __shfl_sync(0xffffffffu, mysrc, j + 2);
            int s3 = __shfl_sync(0xffffffffu, mysrc, j + 3);
            float w0 = __shfl_sync(0xffffffffu, myw, j);
            float w1 = __shfl_sync(0xffffffffu, myw, j + 1);
            float w2 = __shfl_sync(0xffffffffu, myw, j + 2);
            float w3 = __shfl_sync(0xffffffffu, myw, j + 3);
            uint4 r0 = *(const uint4*)(hw + (size_t)s0 * ldh + lane * 8);
            uint4 r1 = *(const uint4*)(hw + (size_t)s1 * ldh + lane * 8);
            uint4 r2 = *(const uint4*)(hw + (size_t)s2 * ldh + lane * 8);
            uint4 r3 = *(const uint4*)(hw + (size_t)s3 * ldh + lane * 8);
            acc8(a, r0, w0); acc8(a, r1, w1); acc8(a, r2, w2); acc8(a, r3, w3);
        }
        for (; j < n; j++) {
            int s  = __shfl_sync(0xffffffffu, mysrc, j);
            float w = __shfl_sync(0xffffffffu, myw, j);
            uint4 raw = *(const uint4*)(hw + (size_t)s * ldh + lane * 8);
            acc8(a, raw, w);
        }
    }

    float4 b0 = *(const float4*)(bias + lane * 8);
    float4 b1 = *(const float4*)(bias + lane * 8 + 4);
    a[0] = fmaxf(a[0] + b0.x, 0.f); a[1] = fmaxf(a[1] + b0.y, 0.f);
    a[2] = fmaxf(a[2] + b0.z, 0.f); a[3] = fmaxf(a[3] + b0.w, 0.f);
    a[4] = fmaxf(a[4] + b1.x, 0.f); a[5] = fmaxf(a[5] + b1.y, 0.f);
    a[6] = fmaxf(a[6] + b1.z, 0.f); a[7] = fmaxf(a[7] + b1.w, 0.f);

    if (ACCUM) {
        float m = *maskPtr;
        float* o = outF + (size_t)v * DH + lane * 8;
        float4 o0 = *(float4*)o, o1 = *(float4*)(o + 4);
        o0.x += a[0] * m; o0.y += a[1] * m; o0.z += a[2] * m; o0.w += a[3] * m;
        o1.x += a[4] * m; o1.y += a[5] * m; o1.z += a[6] * m; o1.w += a[7] * m;
        *(float4*)o = o0; *(float4*)(o + 4) = o1;
    } else {
        uint4 pk;
        bf162* pp = (bf162*)&pk;
        pp[0] = __float22bfloat162_rn(make_float2(a[0], a[1]));
        pp[1] = __float22bfloat162_rn(make_float2(a[2], a[3]));
        pp[2] = __float22bfloat162_rn(make_float2(a[4], a[5]));
        pp[3] = __float22bfloat162_rn(make_float2(a[6], a[7]));
        *(uint4*)(outB + (size_t)v * DH + lane * 8) = pk;
    }
}

// dual-slice agg over graph 2: slice0 (cols 0-255) -> g_h (b_init, relu, bf16)
//                              slice3 (cols 768-1023) -> acc += relu(+bc2)*mask2
__global__ void __launch_bounds__(256)
k_agg2(const int* __restrict__ rowptr, const int* __restrict__ colidx,
       const float* __restrict__ dinv, const bf16* __restrict__ C,
       const float* __restrict__ bias0, const float* __restrict__ bias3,
       const float* __restrict__ maskPtr,
       bf16* __restrict__ outB, float* __restrict__ outF) {
    int v = blockIdx.x * 8 + (threadIdx.x >> 5);
    if (v >= NN) return;
    int lane = threadIdx.x & 31;
    float dv = dinv[v];
    int e0 = rowptr[v], e1 = rowptr[v + 1];

    float a0[8], a3[8];
    {
        float wsl = dv * dv;
        const bf16* rowp = C + (size_t)v * NC + lane * 8;
        uint4 p0 = *(const uint4*)rowp;
        uint4 p3 = *(const uint4*)(rowp + 768);
        const bf162* q0 = (const bf162*)&p0;
        const bf162* q3 = (const bf162*)&p3;
#pragma unroll
        for (int t = 0; t < 4; t++) {
            float2 f0 = __bfloat1622float2(q0[t]);
            float2 f3 = __bfloat1622float2(q3[t]);
            a0[2 * t] = f0.x * wsl; a0[2 * t + 1] = f0.y * wsl;
            a3[2 * t] = f3.x * wsl; a3[2 * t + 1] = f3.y * wsl;
        }
    }

    for (int base = e0; base < e1; base += 32) {
        int idx = base + lane;
        int mysrc = 0; float myw = 0.f;
        if (idx < e1) { mysrc = colidx[idx]; myw = dinv[mysrc] * dv; }
        int n = min(32, e1 - base);
        int j = 0;
        for (; j + 1 < n; j += 2) {
            int sa = __shfl_sync(0xffffffffu, mysrc, j);
            int sb = __shfl_sync(0xffffffffu, mysrc, j + 1);
            float wa = __shfl_sync(0xffffffffu, myw, j);
            float wb = __shfl_sync(0xffffffffu, myw, j + 1);
            const bf16* ra = C + (size_t)sa * NC + lane * 8;
            const bf16* rb = C + (size_t)sb * NC + lane * 8;
            uint4 pa0 = *(const uint4*)ra;
            uint4 pa3 = *(const uint4*)(ra + 768);
            uint4 pb0 = *(const uint4*)rb;
            uint4 pb3 = *(const uint4*)(rb + 768);
            acc8(a0, pa0, wa); acc8(a3, pa3, wa);
            acc8(a0, pb0, wb); acc8(a3, pb3, wb);
        }
        for (; j < n; j++) {
            int s  = __shfl_sync(0xffffffffu, mysrc, j);
            float w = __shfl_sync(0xffffffffu, myw, j);
            const bf16* r = C + (size_t)s * NC + lane * 8;
            uint4 p0 = *(const uint4*)r;
            uint4 p3 = *(const uint4*)(r + 768);
            acc8(a0, p0, w); acc8(a3, p3, w);
        }
    }

    // slice0 -> g_h (bf16)
    {
        float4 b0 = *(const float4*)(bias0 + lane * 8);
        float4 b1 = *(const float4*)(bias0 + lane * 8 + 4);
        float r[8];
        r[0] = fmaxf(a0[0] + b0.x, 0.f); r[1] = fmaxf(a0[1] + b0.y, 0.f);
        r[2] = fmaxf(a0[2] + b0.z, 0.f); r[3] = fmaxf(a0[3] + b0.w, 0.f);
        r[4] = fmaxf(a0[4] + b1.x, 0.f); r[5] = fmaxf(a0[5] + b1.y, 0.f);
        r[6] = fmaxf(a0[6] + b1.z, 0.f); r[7] = fmaxf(a0[7] + b1.w, 0.f);
        uint4 pk;
        bf162* pp = (bf162*)&pk;
        pp[0] = __float22bfloat162_rn(make_float2(r[0], r[1]));
        pp[1] = __float22bfloat162_rn(make_float2(r[2], r[3]));
        pp[2] = __float22bfloat162_rn(make_float2(r[4], r[5]));
        pp[3] = __float22bfloat162_rn(make_float2(r[6], r[7]));
        *(uint4*)(outB + (size_t)v * DH + lane * 8) = pk;
    }
    // slice3 -> acc
    {
        float m = *maskPtr;
        float4 b0 = *(const float4*)(bias3 + lane * 8);
        float4 b1 = *(const float4*)(bias3 + lane * 8 + 4);
        float r[8];
        r[0] = fmaxf(a3[0] + b0.x, 0.f); r[1] = fmaxf(a3[1] + b0.y, 0.f);
        r[2] = fmaxf(a3[2] + b0.z, 0.f); r[3] = fmaxf(a3[3] + b0.w, 0.f);
        r[4] = fmaxf(a3[4] + b1.x, 0.f); r[5] = fmaxf(a3[5] + b1.y, 0.f);
        r[6] = fmaxf(a3[6] + b1.z, 0.f); r[7] = fmaxf(a3[7] + b1.w, 0.f);
        float* o = outF + (size_t)v * DH + lane * 8;
        float4 o0 = *(float4*)o, o1 = *(float4*)(o + 4);
        o0.x += r[0] * m; o0.y += r[1] * m; o0.z += r[2] * m; o0.w += r[3] * m;
        o1.x += r[4] * m; o1.y += r[5] * m; o1.z += r[6] * m; o1.w += r[7] * m;
        *(float4*)o = o0; *(float4*)(o + 4) = o1;
    }
}

// ---------------- bf16 tensor-core GEMM (ldmatrix fragment loads) -----------
__device__ __forceinline__ void cpa16(uint32_t dst, const void* src, bool pred) {
    int sz = pred ? 16 : 0;
    asm volatile("cp.async.cg.shared.global [%0], [%1], 16, %2;\n"
                 :: "r"(dst), "l"(src), "r"(sz));
}

__device__ __forceinline__ uint32_t pack_bf2(float lo, float hi) {
    bf162 t = __float22bfloat162_rn(make_float2(lo, hi));
    uint32_t u = *reinterpret_cast<uint32_t*>(&t);
    return u;
}

__device__ __forceinline__ void ldsm_x4(uint32_t& r0, uint32_t& r1,
                                        uint32_t& r2, uint32_t& r3, uint32_t addr) {
    asm volatile("ldmatrix.sync.aligned.m8n8.x4.shared.b16 {%0,%1,%2,%3}, [%4];\n"
                 : "=r"(r0), "=r"(r1), "=r"(r2), "=r"(r3) : "r"(addr));
}

#define STQ 40   // smem k-stride in halves (80B rows -> conflict-free)

template <bool BIAS, bool RELU, bool SCALE, bool OUTBF>
__global__ void __launch_bounds__(256, 2)
gemm_bf16(const bf16* __restrict__ A, const bf16* __restrict__ Bt,
          const float* __restrict__ bias, const float* __restrict__ scalePtr,
          void* __restrict__ Cv, int M, int N, int K,
          int lda, int ldbt, int ldc, int col0) {
    __shared__ bf16 As[2][128 * STQ];
    __shared__ bf16 Bs[2][128 * STQ];

    const int tid = threadIdx.x;
    const int bm  = blockIdx.y * 128;
    const int bn  = blockIdx.x * 128;
    const int wid = tid >> 5, lane = tid & 31;
    const int wm  = (wid >> 1) * 32;
    const int wn  = (wid & 1) * 64;
    const int g   = lane >> 2, q = lane & 3;

    // ldmatrix lane offsets
    const int rA = (lane & 7) + ((lane >> 3) & 1) * 8;
    const int kA = (lane >> 4) * 8;
    const int rB = (lane & 7) + (lane >> 4) * 8;
    const int kB = ((lane >> 3) & 1) * 8;

    float4 acc[2][8];
#pragma unroll
    for (int i = 0; i < 2; i++)
#pragma unroll
        for (int j = 0; j < 8; j++) acc[i][j] = make_float4(0.f, 0.f, 0.f, 0.f);

    const uint32_t sA = (uint32_t)__cvta_generic_to_shared(&As[0][0]);
    const uint32_t sB = (uint32_t)__cvta_generic_to_shared(&Bs[0][0]);
    const uint32_t bufSz = 128 * STQ * 2;

    const int T = K / 32;

    auto load_tile = [&](int t, int buf) {
        int k0 = t * 32;
#pragma unroll
        for (int i = 0; i < 2; i++) {
            int c = tid + i * 256;
            int row = c >> 2, kx = (c & 3) * 8;
            const bf16* srcp = A + (size_t)(bm + row) * lda + k0 + kx;
            cpa16(sA + buf * bufSz + (uint32_t)(row * STQ + kx) * 2, srcp, bm + row < M);
        }
#pragma unroll
        for (int i = 0; i < 2; i++) {
            int c = tid + i * 256;
            int row = c >> 2, kx = (c & 3) * 8;
            const bf16* srcp = Bt + (size_t)(bn + row) * ldbt + k0 + kx;
            cpa16(sB + buf * bufSz + (uint32_t)(row * STQ + kx) * 2, srcp, true);
        }
    };

    load_tile(0, 0);
    asm volatile("cp.async.commit_group;\n" ::);

    for (int t = 0; t < T; t++) {
        if (t + 1 < T) {
            load_tile(t + 1, (t + 1) & 1);
            asm volatile("cp.async.commit_group;\n" ::);
            asm volatile("cp.async.wait_group 1;\n" ::);
        } else {
            asm volatile("cp.async.wait_group 0;\n" ::);
        }
        __syncthreads();

        const uint32_t asb = sA + (t & 1) * bufSz;
        const uint32_t bsb = sB + (t & 1) * bufSz;
#pragma unroll
        for (int kp = 0; kp < 2; kp++) {
            const int kb = kp * 16;
            uint32_t a[2][4], b[8][2];
#pragma unroll
            for (int i = 0; i < 2; i++) {
                uint32_t addr = asb + (uint32_t)(((wm + i * 16 + rA) * STQ + kb + kA) * 2);
                ldsm_x4(a[i][0], a[i][1], a[i][2], a[i][3], addr);
            }
#pragma unroll
            for (int jj = 0; jj < 4; jj++) {
                uint32_t addr = bsb + (uint32_t)(((wn + jj * 16 + rB) * STQ + kb + kB) * 2);
                ldsm_x4(b[2 * jj][0], b[2 * jj][1], b[2 * jj + 1][0], b[2 * jj + 1][1], addr);
            }
#pragma unroll
            for (int i = 0; i < 2; i++)
#pragma unroll
                for (int j = 0; j < 8; j++) {
                    asm volatile(
                        "mma.sync.aligned.m16n8k16.row.col.f32.bf16.bf16.f32 "
                        "{%0,%1,%2,%3},{%4,%5,%6,%7},{%8,%9},{%0,%1,%2,%3};"
                        : "+f"(acc[i][j].x), "+f"(acc[i][j].y),
                          "+f"(acc[i][j].z), "+f"(acc[i][j].w)
                        : "r"(a[i][0]), "r"(a[i][1]), "r"(a[i][2]), "r"(a[i][3]),
                          "r"(b[j][0]), "r"(b[j][1]));
                }
        }
        __syncthreads();
    }

    float scale = SCALE ? *scalePtr : 1.f;
#pragma unroll
    for (int i = 0; i < 2; i++) {
#pragma unroll
        for (int j = 0; j < 8; j++) {
            int col = bn + wn + j * 8 + q * 2;
            bool ep = (col >= col0);
            float b0 = 0.f, b1 = 0.f;
            if (BIAS && ep) { b0 = bias[col - col0]; b1 = bias[col + 1 - col0]; }
            int r0 = bm + wm + i * 16 + g;
            int r1 = r0 + 8;
            float v0 = acc[i][j].x, v1 = acc[i][j].y;
            float v2 = acc[i][j].z, v3 = acc[i][j].w;
            if (BIAS && ep) { v0 += b0; v1 += b1; v2 += b0; v3 += b1; }
            if (RELU && ep) {
                v0 = fmaxf(v0, 0.f); v1 = fmaxf(v1, 0.f);
                v2 = fmaxf(v2, 0.f); v3 = fmaxf(v3, 0.f);
            }
            if (SCALE) { v0 *= scale; v1 *= scale; v2 *= scale; v3 *= scale; }
            if (OUTBF) {
                bf16* C = (bf16*)Cv;
                if (r0 < M) *(uint32_t*)(C + (size_t)r0 * ldc + col) = pack_bf2(v0, v1);
                if (r1 < M) *(uint32_t*)(C + (size_t)r1 * ldc + col) = pack_bf2(v2, v3);
            } else {
                float* C = (float*)Cv;
                if (r0 < M) *(float2*)(C + (size_t)r0 * ldc + col) = make_float2(v0, v1);
                if (r1 < M) *(float2*)(C + (size_t)r1 * ldc + col) = make_float2(v2, v3);
            }
        }
    }
}

// ---------------- tf32 GEMM for fc1 (fp32 A/B) ------------------------------
__device__ __forceinline__ uint32_t f2tf(float f) {
    uint32_t u; asm("cvt.rna.tf32.f32 %0, %1;" : "=r"(u) : "f"(f)); return u;
}
#define AS_STRIDE 20
#define BS_STRIDE 136

__global__ void __launch_bounds__(256, 2)
gemm_fc1(const float* __restrict__ A, const float* __restrict__ B,
         const float* __restrict__ bias, float* __restrict__ C,
         int M, int N, int K, int lda, int ldb, int ldc) {
    __shared__ float As2[2][128 * AS_STRIDE];
    __shared__ float Bs2[2][16 * BS_STRIDE];

    const int tid = threadIdx.x;
    const int bm  = blockIdx.y * 128;
    const int bn  = 0;
    const int wid = tid >> 5, lane = tid & 31;
    const int wm  = (wid >> 1) * 32;
    const int wn  = (wid & 1) * 64;
    const int g   = lane >> 2, q = lane & 3;

    float4 acc[2][8];
#pragma unroll
    for (int i = 0; i < 2; i++)
#pragma unroll
        for (int j = 0; j < 8; j++) acc[i][j] = make_float4(0.f, 0.f, 0.f, 0.f);

    const uint32_t sA = (uint32_t)__cvta_generic_to_shared(&As2[0][0]);
    const uint32_t sB = (uint32_t)__cvta_generic_to_shared(&Bs2[0][0]);
    const uint32_t aBufSz = 128 * AS_STRIDE * 4;
    const uint32_t bBufSz = 16 * BS_STRIDE * 4;
    const int T = (K + 15) / 16;

    auto load_tile = [&](int t, int buf) {
        int k0 = t * 16;
#pragma unroll
        for (int i = 0; i < 2; i++) {
            int c = tid + i * 256;
            int m = c >> 2, k = (c & 3) * 4;
            const float* srcp = A + (size_t)(bm + m) * lda + k0 + k;
            bool p = (bm + m < M) && (k0 + k < K);
            cpa16(sA + buf * aBufSz + (uint32_t)(m * AS_STRIDE + k) * 4, srcp, p);
        }
#pragma unroll
        for (int i = 0; i < 2; i++) {
            int c = tid + i * 256;
            int kk = c >> 5, n = (c & 31) * 4;
            const float* srcp = B + (size_t)(k0 + kk) * ldb + bn + n;
            bool p = (k0 + kk < K) && (bn + n < N);
            cpa16(sB + buf * bBufSz + (uint32_t)(kk * BS_STRIDE + n) * 4, srcp, p);
        }
    };

    load_tile(0, 0);
    asm volatile("cp.async.commit_group;\n" ::);

    for (int t = 0; t < T; t++) {
        if (t + 1 < T) {
            load_tile(t + 1, (t + 1) & 1);
            asm volatile("cp.async.commit_group;\n" ::);
            asm volatile("cp.async.wait_group 1;\n" ::);
        } else {
            asm volatile("cp.async.wait_group 0;\n" ::);
        }
        __syncthreads();
        const float* as = As2[t & 1];
        const float* bs = Bs2[t & 1];
#pragma unroll
        for (int kp = 0; kp < 2; kp++) {
            const int kb = kp * 8;
            uint32_t a[2][4], b[8][2];
#pragma unroll
            for (int i = 0; i < 2; i++) {
                int m0 = wm + i * 16;
                a[i][0] = f2tf(as[(m0 + g) * AS_STRIDE + kb + q]);
                a[i][1] = f2tf(as[(m0 + g + 8) * AS_STRIDE + kb + q]);
                a[i][2] = f2tf(as[(m0 + g) * AS_STRIDE + kb + q + 4]);
                a[i][3] = f2tf(as[(m0 + g + 8) * AS_STRIDE + kb + q + 4]);
            }
#pragma unroll
            for (int j = 0; j < 8; j++) {
                int n0 = wn + j * 8;
                b[j][0] = f2tf(bs[(kb + q) * BS_STRIDE + n0 + g]);
                b[j][1] = f2tf(bs[(kb + q + 4) * BS_STRIDE + n0 + g]);
            }
#pragma unroll
            for (int i = 0; i < 2; i++)
#pragma unroll
                for (int j = 0; j < 8; j++) {
                    asm volatile(
                        "mma.sync.aligned.m16n8k8.row.col.f32.tf32.tf32.f32 "
                        "{%0,%1,%2,%3},{%4,%5,%6,%7},{%8,%9},{%0,%1,%2,%3};"
                        : "+f"(acc[i][j].x), "+f"(acc[i][j].y),
                          "+f"(acc[i][j].z), "+f"(acc[i][j].w)
                        : "r"(a[i][0]), "r"(a[i][1]), "r"(a[i][2]), "r"(a[i][3]),
                          "r"(b[j][0]), "r"(b[j][1]));
                }
        }
        __syncthreads();
    }

#pragma unroll
    for (int i = 0; i < 2; i++) {
#pragma unroll
        for (int j = 0; j < 8; j++) {
            int col = bn + wn + j * 8 + q * 2;
            if (col >= N) continue;
            float b0 = bias[col], b1 = bias[col + 1];
            int r0 = bm + wm + i * 16 + g;
            int r1 = r0 + 8;
            if (r0 < M) *(float2*)(C + (size_t)r0 * ldc + col) =
                make_float2(acc[i][j].x + b0, acc[i][j].y + b1);
            if (r1 < M) *(float2*)(C + (size_t)r1 * ldc + col) =
                make_float2(acc[i][j].z + b0, acc[i][j].w + b1);
        }
    }
}

// ---------------- in-place log-softmax over rows of 40 ----------------------
__global__ void k_lsm(float* __restrict__ p, int M) {
    int row = blockIdx.x * 8 + (threadIdx.x >> 5);
    int lane = threadIdx.x & 31;
    if (row >= M) return;
    float* r = p + (size_t)row * DOUT;
    float x0 = r[lane];
    float x1 = (lane < 8) ? r[lane + 32] : -1e30f;
    float m = fmaxf(x0, x1);
#pragma unroll
    for (int o = 16; o > 0; o >>= 1) m = fmaxf(m, __shfl_xor_sync(0xffffffffu, m, o));
    float s = expf(x0 - m) + ((lane < 8) ? expf(x1 - m) : 0.f);
#pragma unroll
    for (int o = 16; o > 0; o >>= 1) s += __shfl_xor_sync(0xffffffffu, s, o);
    float l = m + logf(s);
    r[lane] = x0 - l;
    if (lane < 8) r[lane + 32] = x1 - l;
}

// ---------------- launch ----------------------------------------------------
extern "C" void kernel_launch(void* const* d_in, const int* in_sizes, int n_in,
                              void* d_out, int out_size) {
    const float* x       = (const float*)d_in[0];
    const int*   ei      = (const int*)  d_in[1];
    const float* att     = (const float*)d_in[2];
    const float* W_mlp   = (const float*)d_in[3];
    const float* b_mlp   = (const float*)d_in[4];
    const float* W_mlp2  = (const float*)d_in[5];
    const float* b_mlp2  = (const float*)d_in[6];
    const float* W_init  = (const float*)d_in[7];
    const float* b_init  = (const float*)d_in[8];
    const float* W_init2 = (const float*)d_in[9];
    const float* b_init2 = (const float*)d_in[10];
    const float* W_convs = (const float*)d_in[11];
    const float* b_convs = (const float*)d_in[12];
    const float* fc1_W   = (const float*)d_in[13];
    const float* fc1_b   = (const float*)d_in[14];
    float* out = (float*)d_out;

    bf16 *Xbp, *Cp, *hp, *hw2p, *Wtp, *W2tp, *Wm2tp;
    float *accp, *dinvp, *maskp;
    int *cntp, *curp, *rpp, *cip;
    cudaGetSymbolAddress((void**)&Xbp,   g_Xb);
    cudaGetSymbolAddress((void**)&Cp,    g_C);
    cudaGetSymbolAddress((void**)&hp,    g_h);
    cudaGetSymbolAddress((void**)&hw2p,  g_hw2);
    cudaGetSymbolAddress((void**)&accp,  g_acc);
    cudaGetSymbolAddress((void**)&Wtp,   g_Wt);
    cudaGetSymbolAddress((void**)&W2tp,  g_W2t);
    cudaGetSymbolAddress((void**)&Wm2tp, g_Wm2t);
    cudaGetSymbolAddress((void**)&dinvp, g_dinv);
    cudaGetSymbolAddress((void**)&maskp, g_mask);
    cudaGetSymbolAddress((void**)&cntp,  g_cnt);
    cudaGetSymbolAddress((void**)&curp,  g_cursor);
    cudaGetSymbolAddress((void**)&rpp,   g_rowptr);
    cudaGetSymbolAddress((void**)&cip,   g_colidx);

    const int T = 256;
    const int Mt = (NN + 127) / 128;
    const int aggB = (NN + 7) / 8;
    const long long prepN = (long long)NN * KP + (long long)NC * KP + 2LL * DH * DH;

    // (1)(2) CSR count phase
    k_zero<<<(3 * NN + T - 1) / T, T>>>(cntp, curp, 3 * NN);
    k_count<<<(3 * NE + T - 1) / T, T>>>(ei, cntp);
    // (3) dtype conversion + weight pack/transpose
    k_prep<<<(int)((prepN + T - 1) / T), T>>>(x, W_init, W_convs, W_mlp, W_init2, W_mlp2,
                                              Xbp, Wtp, W2tp, Wm2tp);
    // (4) big packed GEMM (ncu-captured launch)
    gemm_bf16<true, true, false, true><<<dim3(NC / 128, Mt), T>>>(
        Xbp, Wtp, b_mlp, nullptr, Cp, NN, NC, KP, KP, KP, NC, 1024);
    // (5)(6) finish CSR
    k_scan<<<3, 1024>>>(cntp, rpp, dinvp);
    k_fillcsr<<<(3 * NE + T - 1) / T, T>>>(ei, rpp, curp, cip);
    // (7) softmax mask
    k_mask<<<1, 32>>>(att);

    // (8) MLP branch initializes acc
    gemm_bf16<true, true, true, false><<<dim3(DH / 128, Mt), T>>>(
        Cp + 1024, Wm2tp, b_mlp2, maskp + 3, accp, NN, DH, DH, NC, DH, DH, 0);

    const int* rp2 = rpp + 2 * (NN + 1);
    const int* ci2 = cip + 2 * NE;
    const float* dv2 = dinvp + 2 * NN;

    // (9) fused hop1 (slice0 -> g_h) + conv2 (slice3 -> acc), both graph 2
    k_agg2<<<aggB, T>>>(rp2, ci2, dv2, Cp, b_init, b_convs + 2 * DH, maskp + 2,
                        hp, accp);
    // (10) hop2 GEMM: hw2 = g_h @ W_init2
    gemm_bf16<false, false, false, true><<<dim3(DH / 128, Mt), T>>>(
        hp, W2tp, nullptr, nullptr, hw2p, NN, DH, DH, DH, DH, DH, 0);
    // (11) hop 2: acc += relu(agg(hw2, graph2) + b_init2) * mask[4]
    k_agg<true><<<aggB, T>>>(rp2, ci2, dv2, hw2p, DH, b_init2, maskp + 4, nullptr, accp);
    // (12)(13) conv0, conv1
    for (int i = 0; i < 2; i++) {
        k_agg<true><<<aggB, T>>>(rpp + i * (NN + 1), cip + i * NE, dinvp + i * NN,
                                 Cp + (1 + i) * 256, NC,
                                 b_convs + (size_t)i * DH, maskp + i, nullptr, accp);
    }

    // (14) logits, (15) log-softmax
    gemm_fc1<<<dim3(1, Mt), T>>>(accp, fc1_W, fc1_b, out, NN, DOUT, DH, DH, DOUT, DOUT);
    k_lsm<<<(NN + 7) / 8, 256>>>(out, NN);
}